// round 1
// baseline (speedup 1.0000x reference)
#include <cuda_runtime.h>
#include <cuda_bf16.h>
#include <math.h>

// Problem constants (shapes fixed by the reference)
#define NN    16384
#define EE    524288
#define F_IN  128
#define H1    256
#define H2    256
#define D1    64

// ---------------- scratch (device globals; no runtime alloc allowed) --------
__device__ float g_deg[NN];
__device__ float g_dinv[NN];
__device__ float g_xw  [NN * 256];   // GEMM output (reused for both layers)
__device__ float g_bufA[NN * 256];   // agg1 -> h1
__device__ float g_bufB[NN * 256];   // agg2 -> h2
__device__ float g_assign[NN * 2];
__device__ float g_group[2 * 256];
__device__ float g_newadj[4];

// ---------------- kernels ---------------------------------------------------

__global__ void zero_kernel() {
    int i = blockIdx.x * blockDim.x + threadIdx.x;
    if (i < NN)  g_deg[i] = 0.0f;
    if (i < 512) g_group[i] = 0.0f;
    if (i < 4)   g_newadj[i] = 0.0f;
}

__global__ void deg_kernel(const int* __restrict__ dst, int E) {
    int e = blockIdx.x * blockDim.x + threadIdx.x;
    if (e < E) atomicAdd(&g_deg[dst[e]], 1.0f);
}

__global__ void dinv_kernel(int n) {
    int i = blockIdx.x * blockDim.x + threadIdx.x;
    if (i < n) g_dinv[i] = rsqrtf(g_deg[i] + 1.0f);   // +1 self-loop; always > 0
}

// Tiled FP32 GEMM: C[M,Nc] = A[M,K] @ B[K,Nc].  BM=BN=64, BK=16, 256 thr, 4x4/thread.
__global__ void gemm_kernel(const float* __restrict__ A, const float* __restrict__ B,
                            float* __restrict__ C, int M, int K, int Nc) {
    __shared__ float As[64][17];
    __shared__ float Bs[16][64];
    const int tid = threadIdx.x;
    const int tx = tid & 15, ty = tid >> 4;
    const int rowBase = blockIdx.y * 64;
    const int colBase = blockIdx.x * 64;

    float acc[4][4];
#pragma unroll
    for (int i = 0; i < 4; i++)
#pragma unroll
        for (int j = 0; j < 4; j++) acc[i][j] = 0.0f;

    for (int k0 = 0; k0 < K; k0 += 16) {
        // load A tile 64x16 (1024 elems / 256 thr = 4)
#pragma unroll
        for (int l = 0; l < 4; l++) {
            int i = tid + l * 256;
            int r = i >> 4, c = i & 15;
            As[r][c] = A[(size_t)(rowBase + r) * K + k0 + c];
        }
        // load B tile 16x64
#pragma unroll
        for (int l = 0; l < 4; l++) {
            int i = tid + l * 256;
            int r = i >> 6, c = i & 63;
            Bs[r][c] = B[(size_t)(k0 + r) * Nc + colBase + c];
        }
        __syncthreads();
#pragma unroll
        for (int kk = 0; kk < 16; kk++) {
            float a[4], b[4];
#pragma unroll
            for (int i = 0; i < 4; i++) a[i] = As[ty * 4 + i][kk];
#pragma unroll
            for (int j = 0; j < 4; j++) b[j] = Bs[kk][tx * 4 + j];
#pragma unroll
            for (int i = 0; i < 4; i++)
#pragma unroll
                for (int j = 0; j < 4; j++) acc[i][j] = fmaf(a[i], b[j], acc[i][j]);
        }
        __syncthreads();
    }
#pragma unroll
    for (int i = 0; i < 4; i++) {
        int r = rowBase + ty * 4 + i;
#pragma unroll
        for (int j = 0; j < 4; j++) {
            C[(size_t)r * Nc + colBase + tx * 4 + j] = acc[i][j];
        }
    }
}

// agg[i] = xw[i] * dinv[i]^2   (self-loop contribution, also initializes agg)
__global__ void initagg_kernel(const float* __restrict__ xw, float* __restrict__ agg, int n) {
    int idx = blockIdx.x * blockDim.x + threadIdx.x;   // over n*64 float4 chunks
    if (idx >= n * 64) return;
    int node = idx >> 6;
    float w = g_dinv[node];
    w = w * w;
    float4 v = ((const float4*)xw)[idx];
    v.x *= w; v.y *= w; v.z *= w; v.w *= w;
    ((float4*)agg)[idx] = v;
}

// atomic scatter over edges: agg[dst] += xw[src] * dinv[src]*dinv[dst]
__global__ void scatter_kernel(const float* __restrict__ xw,
                               const int* __restrict__ src, const int* __restrict__ dst,
                               float* __restrict__ agg, int E) {
    long long idx = (long long)blockIdx.x * blockDim.x + threadIdx.x;
    int e = (int)(idx >> 6);       // 64 float4 chunks of 256 feats
    if (e >= E) return;
    int c = (int)(idx & 63);
    int s = src[e], d = dst[e];
    float w = g_dinv[s] * g_dinv[d];
    float4 v = ((const float4*)(xw + (size_t)s * 256))[c];
    float* o = agg + (size_t)d * 256 + c * 4;
    atomicAdd(o + 0, v.x * w);
    atomicAdd(o + 1, v.y * w);
    atomicAdd(o + 2, v.z * w);
    atomicAdd(o + 3, v.w * w);
}

template <bool RELU>
__global__ void bias_act_kernel(float* __restrict__ x, const float* __restrict__ b, int n) {
    int idx = blockIdx.x * blockDim.x + threadIdx.x;  // over n*256
    if (idx >= n * 256) return;
    float v = x[idx] + b[idx & 255];
    if (RELU) v = fmaxf(v, 0.0f);
    x[idx] = v;
}

// per-node: a1 = tanh(h2 @ fc1_w^T + fc1_b) [64]; logits = a1 @ fc2_w^T + fc2_b [2]; softmax
__global__ void mlp_kernel(const float* __restrict__ h2,
                           const float* __restrict__ fc1w, const float* __restrict__ fc1b,
                           const float* __restrict__ fc2w, const float* __restrict__ fc2b) {
    int i = blockIdx.x;
    int t = threadIdx.x;            // 64 threads
    __shared__ float row[256];
    __shared__ float a1s[64];
    __shared__ float logits[2];
#pragma unroll
    for (int f = t; f < 256; f += 64) row[f] = h2[(size_t)i * 256 + f];
    __syncthreads();
    float acc = fc1b[t];
    const float* wr = fc1w + (size_t)t * 256;
#pragma unroll 8
    for (int k = 0; k < 256; k++) acc = fmaf(row[k], wr[k], acc);
    a1s[t] = tanhf(acc);
    __syncthreads();
    if (t < 2) {
        float l = fc2b[t];
        const float* w2 = fc2w + t * 64;
#pragma unroll
        for (int k = 0; k < 64; k++) l = fmaf(a1s[k], w2[k], l);
        logits[t] = l;
    }
    __syncthreads();
    if (t == 0) {
        float l0 = logits[0], l1 = logits[1];
        float m = fmaxf(l0, l1);
        float e0 = __expf(l0 - m), e1 = __expf(l1 - m);
        float inv = 1.0f / (e0 + e1);
        g_assign[i * 2 + 0] = e0 * inv;
        g_assign[i * 2 + 1] = e1 * inv;
    }
}

// group_features[a,:] = sum_i assign[i,a] * h2[i,:]
__global__ void group_kernel(const float* __restrict__ h2, int n) {
    int t = threadIdx.x;   // 256
    float acc0 = 0.0f, acc1 = 0.0f;
    for (int i = blockIdx.x; i < n; i += gridDim.x) {
        float a0 = g_assign[i * 2], a1 = g_assign[i * 2 + 1];
        float v = h2[(size_t)i * 256 + t];
        acc0 = fmaf(a0, v, acc0);
        acc1 = fmaf(a1, v, acc1);
    }
    atomicAdd(&g_group[t], acc0);
    atomicAdd(&g_group[256 + t], acc1);
}

// new_adj[a,b] = sum_e assign[src_e,a] * assign[dst_e,b]
__global__ void newadj_kernel(const int* __restrict__ src, const int* __restrict__ dst, int E) {
    float s00 = 0, s01 = 0, s10 = 0, s11 = 0;
    for (int e = blockIdx.x * blockDim.x + threadIdx.x; e < E; e += gridDim.x * blockDim.x) {
        int s = src[e], d = dst[e];
        float as0 = g_assign[s * 2], as1 = g_assign[s * 2 + 1];
        float ad0 = g_assign[d * 2], ad1 = g_assign[d * 2 + 1];
        s00 = fmaf(as0, ad0, s00);
        s01 = fmaf(as0, ad1, s01);
        s10 = fmaf(as1, ad0, s10);
        s11 = fmaf(as1, ad1, s11);
    }
#pragma unroll
    for (int off = 16; off > 0; off >>= 1) {
        s00 += __shfl_down_sync(0xffffffffu, s00, off);
        s01 += __shfl_down_sync(0xffffffffu, s01, off);
        s10 += __shfl_down_sync(0xffffffffu, s10, off);
        s11 += __shfl_down_sync(0xffffffffu, s11, off);
    }
    __shared__ float sh[4][8];
    int lane = threadIdx.x & 31, w = threadIdx.x >> 5;
    if (lane == 0) { sh[0][w] = s00; sh[1][w] = s01; sh[2][w] = s10; sh[3][w] = s11; }
    __syncthreads();
    if (threadIdx.x < 4) {
        float sum = 0;
        int nw = blockDim.x >> 5;
        for (int k = 0; k < nw; k++) sum += sh[threadIdx.x][k];
        atomicAdd(&g_newadj[threadIdx.x], sum);
    }
}

// out = [graph_embedding(256), positive(256), negative(256), pos_penalty(1)]
__global__ void final_kernel(float* __restrict__ out) {
    int t = threadIdx.x;   // 256
    float g0 = g_group[t], g1 = g_group[256 + t];
    out[t]        = 0.5f * (g0 + g1);
    out[256 + t]  = fminf(fmaxf(g0, -100.0f), 100.0f);
    out[512 + t]  = fminf(fmaxf(g1, -100.0f), 100.0f);
    if (t == 0) {
        float n00 = g_newadj[0], n01 = g_newadj[1];
        float n10 = g_newadj[2], n11 = g_newadj[3];
        float d0 = fmaxf(fabsf(n00) + fabsf(n01), 1e-12f);
        float d1 = fmaxf(fabsf(n10) + fabsf(n11), 1e-12f);
        float diag0 = n00 / d0 - 1.0f;
        float diag1 = n11 / d1 - 1.0f;
        out[768] = 0.5f * (diag0 * diag0 + diag1 * diag1);
    }
}

// ---------------- launch ----------------------------------------------------

extern "C" void kernel_launch(void* const* d_in, const int* in_sizes, int n_in,
                              void* d_out, int out_size) {
    const float* features = (const float*)d_in[0];
    const int*   edges    = (const int*)d_in[1];
    const float* W1   = (const float*)d_in[2];
    const float* b1   = (const float*)d_in[3];
    const float* W2   = (const float*)d_in[4];
    const float* b2   = (const float*)d_in[5];
    const float* fc1w = (const float*)d_in[6];
    const float* fc1b = (const float*)d_in[7];
    const float* fc2w = (const float*)d_in[8];
    const float* fc2b = (const float*)d_in[9];
    float* out = (float*)d_out;

    const int n = in_sizes[0] / F_IN;       // 16384
    const int E = in_sizes[1] / 2;          // 524288
    const int* src = edges;
    const int* dst = edges + E;

    float *xw, *bufA, *bufB;
    cudaGetSymbolAddress((void**)&xw,   g_xw);
    cudaGetSymbolAddress((void**)&bufA, g_bufA);
    cudaGetSymbolAddress((void**)&bufB, g_bufB);

    // degrees + dinv
    zero_kernel<<<(NN + 255) / 256, 256>>>();
    deg_kernel<<<(E + 255) / 256, 256>>>(dst, E);
    dinv_kernel<<<(n + 255) / 256, 256>>>(n);

    // ---- layer 1: relu(D^-1/2 (A+I) D^-1/2 (X W1) + b1)
    {
        dim3 grid(H1 / 64, n / 64);
        gemm_kernel<<<grid, 256>>>(features, W1, xw, n, F_IN, H1);
    }
    initagg_kernel<<<(n * 64 + 255) / 256, 256>>>(xw, bufA, n);
    {
        long long tot = (long long)E * 64;
        scatter_kernel<<<(unsigned)((tot + 255) / 256), 256>>>(xw, src, dst, bufA, E);
    }
    bias_act_kernel<true><<<(n * 256 + 255) / 256, 256>>>(bufA, b1, n);

    // ---- layer 2: D^-1/2 (A+I) D^-1/2 (h1 W2) + b2
    {
        dim3 grid(H2 / 64, n / 64);
        gemm_kernel<<<grid, 256>>>(bufA, W2, xw, n, H1, H2);
    }
    initagg_kernel<<<(n * 64 + 255) / 256, 256>>>(xw, bufB, n);
    {
        long long tot = (long long)E * 64;
        scatter_kernel<<<(unsigned)((tot + 255) / 256), 256>>>(xw, src, dst, bufB, E);
    }
    bias_act_kernel<false><<<(n * 256 + 255) / 256, 256>>>(bufB, b2, n);

    // ---- assignment MLP + softmax
    mlp_kernel<<<n, 64>>>(bufB, fc1w, fc1b, fc2w, fc2b);

    // ---- group features + 2x2 pooled adjacency
    group_kernel<<<256, 256>>>(bufB, n);
    newadj_kernel<<<256, 256>>>(src, dst, E);

    // ---- outputs
    final_kernel<<<1, 256>>>(out);
}

// round 2
// speedup vs baseline: 5.8866x; 5.8866x over previous
#include <cuda_runtime.h>
#include <cuda_bf16.h>
#include <math.h>

#define NN    16384
#define EE    524288
#define F_IN  128
#define H1    256
#define H2    256
#define D1    64

// ---------------- scratch (device globals) ----------------------------------
__device__ int   g_degi[NN];
__device__ int   g_rowstart[NN + 1];
__device__ int   g_cursor[NN];
__device__ int   g_csrc[EE];
__device__ float g_cw[EE];
__device__ float g_dinv[NN];
__device__ float g_fc1wT[256 * 64];
__device__ float g_xw  [NN * 256];
__device__ float g_bufA[NN * 256];
__device__ float g_bufB[NN * 256];
__device__ float g_assign[NN * 2];
__device__ float g_group[2 * 256];
__device__ float g_newadj[4];

// ---------------- setup kernels ---------------------------------------------

__global__ void zero_kernel() {
    int i = blockIdx.x * blockDim.x + threadIdx.x;
    if (i < NN)  g_degi[i] = 0;
    if (i < 512) g_group[i] = 0.0f;
    if (i < 4)   g_newadj[i] = 0.0f;
}

__global__ void deg_kernel(const int* __restrict__ dst, int E) {
    int e = blockIdx.x * blockDim.x + threadIdx.x;
    if (e < E) atomicAdd(&g_degi[dst[e]], 1);
}

__global__ void dinv_kernel(int n) {
    int i = blockIdx.x * blockDim.x + threadIdx.x;
    if (i < n) g_dinv[i] = rsqrtf((float)g_degi[i] + 1.0f);  // +1 self loop
}

// exclusive scan of g_degi (16384 ints) with ONE block of 512 threads
__global__ void scan_kernel() {
    __shared__ int part[512];
    int t = threadIdx.x;
    int base = t * 32;
    int pre[32];
    int sum = 0;
#pragma unroll
    for (int j = 0; j < 32; j++) { pre[j] = sum; sum += g_degi[base + j]; }
    part[t] = sum;
    __syncthreads();
    int total = sum;
    for (int off = 1; off < 512; off <<= 1) {
        int v = (t >= off) ? part[t - off] : 0;
        __syncthreads();
        part[t] += v;
        __syncthreads();
    }
    int offset = part[t] - total;  // exclusive prefix
#pragma unroll
    for (int j = 0; j < 32; j++) {
        int v = offset + pre[j];
        g_rowstart[base + j] = v;
        g_cursor[base + j] = v;
    }
    if (t == 511) g_rowstart[NN] = part[511];
}

__global__ void fill_kernel(const int* __restrict__ src, const int* __restrict__ dst, int E) {
    int e = blockIdx.x * blockDim.x + threadIdx.x;
    if (e >= E) return;
    int s = src[e], d = dst[e];
    int p = atomicAdd(&g_cursor[d], 1);
    g_csrc[p] = s;
    g_cw[p] = g_dinv[s] * g_dinv[d];
}

__global__ void transpose_fc1_kernel(const float* __restrict__ fc1w) {
    int idx = blockIdx.x * blockDim.x + threadIdx.x;
    if (idx < 64 * 256) {
        int j = idx >> 8, k = idx & 255;
        g_fc1wT[k * 64 + j] = fc1w[idx];
    }
}

// ---------------- GEMM (unchanged: already ~52 TF/s fp32) -------------------
__global__ void gemm_kernel(const float* __restrict__ A, const float* __restrict__ B,
                            float* __restrict__ C, int M, int K, int Nc) {
    __shared__ float As[64][17];
    __shared__ float Bs[16][64];
    const int tid = threadIdx.x;
    const int tx = tid & 15, ty = tid >> 4;
    const int rowBase = blockIdx.y * 64;
    const int colBase = blockIdx.x * 64;

    float acc[4][4];
#pragma unroll
    for (int i = 0; i < 4; i++)
#pragma unroll
        for (int j = 0; j < 4; j++) acc[i][j] = 0.0f;

    for (int k0 = 0; k0 < K; k0 += 16) {
#pragma unroll
        for (int l = 0; l < 4; l++) {
            int i = tid + l * 256;
            int r = i >> 4, c = i & 15;
            As[r][c] = A[(size_t)(rowBase + r) * K + k0 + c];
        }
#pragma unroll
        for (int l = 0; l < 4; l++) {
            int i = tid + l * 256;
            int r = i >> 6, c = i & 63;
            Bs[r][c] = B[(size_t)(k0 + r) * Nc + colBase + c];
        }
        __syncthreads();
#pragma unroll
        for (int kk = 0; kk < 16; kk++) {
            float a[4], b[4];
#pragma unroll
            for (int i = 0; i < 4; i++) a[i] = As[ty * 4 + i][kk];
#pragma unroll
            for (int j = 0; j < 4; j++) b[j] = Bs[kk][tx * 4 + j];
#pragma unroll
            for (int i = 0; i < 4; i++)
#pragma unroll
                for (int j = 0; j < 4; j++) acc[i][j] = fmaf(a[i], b[j], acc[i][j]);
        }
        __syncthreads();
    }
#pragma unroll
    for (int i = 0; i < 4; i++) {
        int r = rowBase + ty * 4 + i;
#pragma unroll
        for (int j = 0; j < 4; j++) {
            C[(size_t)r * Nc + colBase + tx * 4 + j] = acc[i][j];
        }
    }
}

// ---------------- gather aggregation (atomic-free) --------------------------
// one 64-thread block per node; float4 per thread; fuses self-loop, bias, act.
template <bool RELU>
__global__ void gather_kernel(const float* __restrict__ xw, const float* __restrict__ bias,
                              float* __restrict__ out) {
    const int i = blockIdx.x;
    const int t = threadIdx.x;   // 0..63
    const float di = g_dinv[i];
    float4 acc = ((const float4*)xw)[i * 64 + t];
    const float w0 = di * di;
    acc.x *= w0; acc.y *= w0; acc.z *= w0; acc.w *= w0;

    int k = g_rowstart[i];
    const int end = g_rowstart[i + 1];
    for (; k + 2 <= end; k += 2) {
        int s0 = g_csrc[k];
        int s1 = g_csrc[k + 1];
        float wa = g_cw[k];
        float wb = g_cw[k + 1];
        float4 v0 = ((const float4*)xw)[s0 * 64 + t];
        float4 v1 = ((const float4*)xw)[s1 * 64 + t];
        acc.x = fmaf(wa, v0.x, acc.x);
        acc.y = fmaf(wa, v0.y, acc.y);
        acc.z = fmaf(wa, v0.z, acc.z);
        acc.w = fmaf(wa, v0.w, acc.w);
        acc.x = fmaf(wb, v1.x, acc.x);
        acc.y = fmaf(wb, v1.y, acc.y);
        acc.z = fmaf(wb, v1.z, acc.z);
        acc.w = fmaf(wb, v1.w, acc.w);
    }
    if (k < end) {
        int s0 = g_csrc[k];
        float wa = g_cw[k];
        float4 v0 = ((const float4*)xw)[s0 * 64 + t];
        acc.x = fmaf(wa, v0.x, acc.x);
        acc.y = fmaf(wa, v0.y, acc.y);
        acc.z = fmaf(wa, v0.z, acc.z);
        acc.w = fmaf(wa, v0.w, acc.w);
    }
    float4 b = ((const float4*)bias)[t];
    acc.x += b.x; acc.y += b.y; acc.z += b.z; acc.w += b.w;
    if (RELU) {
        acc.x = fmaxf(acc.x, 0.0f);
        acc.y = fmaxf(acc.y, 0.0f);
        acc.z = fmaxf(acc.z, 0.0f);
        acc.w = fmaxf(acc.w, 0.0f);
    }
    ((float4*)out)[i * 64 + t] = acc;
}

// ---------------- assignment MLP: 4 nodes/block, 64 threads -----------------
__global__ void mlp_kernel(const float* __restrict__ h2,
                           const float* __restrict__ fc1b,
                           const float* __restrict__ fc2w, const float* __restrict__ fc2b) {
    __shared__ float s_row[4][256];
    __shared__ float s_a1[4][64];
    __shared__ float s_logit[4][2];
    const int t = threadIdx.x;      // 0..63
    const int i0 = blockIdx.x * 4;

#pragma unroll
    for (int l = 0; l < 4; l++) {
        int idx = t + l * 64;       // 0..255 float4 index over 4 rows
        float4 v = ((const float4*)(h2 + (size_t)i0 * 256))[idx];
        ((float4*)&s_row[0][0])[idx] = v;
    }
    __syncthreads();

    float a0 = 0.f, a1 = 0.f, a2 = 0.f, a3 = 0.f;
#pragma unroll 4
    for (int kk = 0; kk < 256; kk++) {
        float wv = g_fc1wT[kk * 64 + t];
        a0 = fmaf(s_row[0][kk], wv, a0);
        a1 = fmaf(s_row[1][kk], wv, a1);
        a2 = fmaf(s_row[2][kk], wv, a2);
        a3 = fmaf(s_row[3][kk], wv, a3);
    }
    const float bb = fc1b[t];
    s_a1[0][t] = tanhf(a0 + bb);
    s_a1[1][t] = tanhf(a1 + bb);
    s_a1[2][t] = tanhf(a2 + bb);
    s_a1[3][t] = tanhf(a3 + bb);
    __syncthreads();

    if (t < 8) {
        int node = t >> 1, j = t & 1;
        float l = fc2b[j];
        const float* w2 = fc2w + j * 64;
#pragma unroll
        for (int kk = 0; kk < 64; kk++) l = fmaf(s_a1[node][kk], w2[kk], l);
        s_logit[node][j] = l;
    }
    __syncthreads();
    if (t < 4) {
        float l0 = s_logit[t][0], l1 = s_logit[t][1];
        float m = fmaxf(l0, l1);
        float e0 = __expf(l0 - m), e1 = __expf(l1 - m);
        float inv = 1.0f / (e0 + e1);
        g_assign[(i0 + t) * 2 + 0] = e0 * inv;
        g_assign[(i0 + t) * 2 + 1] = e1 * inv;
    }
}

// ---------------- pooled reductions ------------------------------------------
__global__ void group_kernel(const float* __restrict__ h2, int n) {
    int t = threadIdx.x;   // 256
    float acc0 = 0.0f, acc1 = 0.0f;
    for (int i = blockIdx.x; i < n; i += gridDim.x) {
        float a0 = g_assign[i * 2], a1 = g_assign[i * 2 + 1];
        float v = h2[(size_t)i * 256 + t];
        acc0 = fmaf(a0, v, acc0);
        acc1 = fmaf(a1, v, acc1);
    }
    atomicAdd(&g_group[t], acc0);
    atomicAdd(&g_group[256 + t], acc1);
}

__global__ void newadj_kernel(const int* __restrict__ src, const int* __restrict__ dst, int E) {
    float s00 = 0, s01 = 0, s10 = 0, s11 = 0;
    for (int e = blockIdx.x * blockDim.x + threadIdx.x; e < E; e += gridDim.x * blockDim.x) {
        int s = src[e], d = dst[e];
        float as0 = g_assign[s * 2], as1 = g_assign[s * 2 + 1];
        float ad0 = g_assign[d * 2], ad1 = g_assign[d * 2 + 1];
        s00 = fmaf(as0, ad0, s00);
        s01 = fmaf(as0, ad1, s01);
        s10 = fmaf(as1, ad0, s10);
        s11 = fmaf(as1, ad1, s11);
    }
#pragma unroll
    for (int off = 16; off > 0; off >>= 1) {
        s00 += __shfl_down_sync(0xffffffffu, s00, off);
        s01 += __shfl_down_sync(0xffffffffu, s01, off);
        s10 += __shfl_down_sync(0xffffffffu, s10, off);
        s11 += __shfl_down_sync(0xffffffffu, s11, off);
    }
    __shared__ float sh[4][8];
    int lane = threadIdx.x & 31, w = threadIdx.x >> 5;
    if (lane == 0) { sh[0][w] = s00; sh[1][w] = s01; sh[2][w] = s10; sh[3][w] = s11; }
    __syncthreads();
    if (threadIdx.x < 4) {
        float sum = 0;
        int nw = blockDim.x >> 5;
        for (int k = 0; k < nw; k++) sum += sh[threadIdx.x][k];
        atomicAdd(&g_newadj[threadIdx.x], sum);
    }
}

__global__ void final_kernel(float* __restrict__ out) {
    int t = threadIdx.x;   // 256
    float g0 = g_group[t], g1 = g_group[256 + t];
    out[t]        = 0.5f * (g0 + g1);
    out[256 + t]  = fminf(fmaxf(g0, -100.0f), 100.0f);
    out[512 + t]  = fminf(fmaxf(g1, -100.0f), 100.0f);
    if (t == 0) {
        float n00 = g_newadj[0], n01 = g_newadj[1];
        float n10 = g_newadj[2], n11 = g_newadj[3];
        float d0 = fmaxf(fabsf(n00) + fabsf(n01), 1e-12f);
        float d1 = fmaxf(fabsf(n10) + fabsf(n11), 1e-12f);
        float diag0 = n00 / d0 - 1.0f;
        float diag1 = n11 / d1 - 1.0f;
        out[768] = 0.5f * (diag0 * diag0 + diag1 * diag1);
    }
}

// ---------------- launch ------------------------------------------------------

extern "C" void kernel_launch(void* const* d_in, const int* in_sizes, int n_in,
                              void* d_out, int out_size) {
    const float* features = (const float*)d_in[0];
    const int*   edges    = (const int*)d_in[1];
    const float* W1   = (const float*)d_in[2];
    const float* b1   = (const float*)d_in[3];
    const float* W2   = (const float*)d_in[4];
    const float* b2   = (const float*)d_in[5];
    const float* fc1w = (const float*)d_in[6];
    const float* fc1b = (const float*)d_in[7];
    const float* fc2w = (const float*)d_in[8];
    const float* fc2b = (const float*)d_in[9];
    float* out = (float*)d_out;

    const int n = in_sizes[0] / F_IN;       // 16384
    const int E = in_sizes[1] / 2;          // 524288
    const int* src = edges;
    const int* dst = edges + E;

    float *xw, *bufA, *bufB;
    cudaGetSymbolAddress((void**)&xw,   g_xw);
    cudaGetSymbolAddress((void**)&bufA, g_bufA);
    cudaGetSymbolAddress((void**)&bufB, g_bufB);

    // ---- graph preprocessing: degrees, dinv, CSR-by-dst
    zero_kernel<<<(NN + 255) / 256, 256>>>();
    deg_kernel<<<(E + 255) / 256, 256>>>(dst, E);
    dinv_kernel<<<(n + 255) / 256, 256>>>(n);
    scan_kernel<<<1, 512>>>();
    fill_kernel<<<(E + 255) / 256, 256>>>(src, dst, E);
    transpose_fc1_kernel<<<(64 * 256 + 255) / 256, 256>>>(fc1w);

    // ---- layer 1: relu(D^-1/2 (A+I) D^-1/2 (X W1) + b1)
    {
        dim3 grid(H1 / 64, n / 64);
        gemm_kernel<<<grid, 256>>>(features, W1, xw, n, F_IN, H1);
    }
    gather_kernel<true><<<n, 64>>>(xw, b1, bufA);

    // ---- layer 2
    {
        dim3 grid(H2 / 64, n / 64);
        gemm_kernel<<<grid, 256>>>(bufA, W2, xw, n, H1, H2);
    }
    gather_kernel<false><<<n, 64>>>(xw, b2, bufB);

    // ---- assignment MLP + softmax
    mlp_kernel<<<n / 4, 64>>>(bufB, fc1b, fc2w, fc2b);

    // ---- pooled reductions
    group_kernel<<<256, 256>>>(bufB, n);
    newadj_kernel<<<256, 256>>>(src, dst, E);

    final_kernel<<<1, 256>>>(out);
}

// round 3
// speedup vs baseline: 6.4389x; 1.0938x over previous
#include <cuda_runtime.h>
#include <cuda_bf16.h>
#include <math.h>

#define NN    16384
#define EE    524288
#define F_IN  128
#define H1    256
#define H2    256
#define D1    64

// ---------------- scratch (device globals) ----------------------------------
__device__ int   g_degi[NN];
__device__ int   g_rowstart[NN + 1];
__device__ int   g_blocksum[64];
__device__ int   g_blockoff[64];
__device__ int   g_cursor[NN];
__device__ int   g_csrc[EE];
__device__ float g_cw[EE];
__device__ float g_dinv[NN];
__device__ float g_fc1wT[256 * 64];
__device__ float g_aggX[NN * F_IN];   // aggregated input features
__device__ float g_xw  [NN * 256];
__device__ float g_bufA[NN * 256];    // h1
__device__ float g_bufB[NN * 256];    // h2
__device__ float g_assign[NN * 2];
__device__ float g_group[2 * 256];
__device__ float g_newadj[4];

// ---------------- setup kernels ---------------------------------------------

__global__ void zero_kernel() {
    int i = blockIdx.x * blockDim.x + threadIdx.x;
    if (i < NN)  g_degi[i] = 0;
    if (i < 512) g_group[i] = 0.0f;
    if (i < 4)   g_newadj[i] = 0.0f;
}

__global__ void deg_kernel(const int* __restrict__ dst, int E) {
    int e = blockIdx.x * blockDim.x + threadIdx.x;
    if (e < E) atomicAdd(&g_degi[dst[e]], 1);
}

__global__ void dinv_kernel(int n) {
    int i = blockIdx.x * blockDim.x + threadIdx.x;
    if (i < n) g_dinv[i] = rsqrtf((float)g_degi[i] + 1.0f);  // +1 self loop
}

// ---- hierarchical exclusive scan of g_degi (16384) -> g_rowstart, g_cursor
__global__ void scan1_kernel() {   // 64 blocks x 256 threads
    const int b = blockIdx.x, t = threadIdx.x;
    const int lane = t & 31, w = t >> 5;
    int v = g_degi[b * 256 + t];
    int s = v;
#pragma unroll
    for (int off = 1; off < 32; off <<= 1) {
        int u = __shfl_up_sync(0xffffffffu, s, off);
        if (lane >= off) s += u;
    }
    __shared__ int ws[8];
    if (lane == 31) ws[w] = s;
    __syncthreads();
    if (t < 8) {
        int x = ws[t];
#pragma unroll
        for (int off = 1; off < 8; off <<= 1) {
            int u = __shfl_up_sync(0xffu, x, off);
            if (t >= off) x += u;
        }
        ws[t] = x;
    }
    __syncthreads();
    int excl = s - v + (w > 0 ? ws[w - 1] : 0);
    g_rowstart[b * 256 + t] = excl;
    if (t == 255) g_blocksum[b] = excl + v;
}

__global__ void scan2_kernel() {   // 1 block x 64 threads
    int t = threadIdx.x;
    int v = g_blocksum[t];
    int s = v;
    int lane = t & 31, w = t >> 5;
#pragma unroll
    for (int off = 1; off < 32; off <<= 1) {
        int u = __shfl_up_sync(0xffffffffu, s, off);
        if (lane >= off) s += u;
    }
    __shared__ int ws[2];
    if (lane == 31) ws[w] = s;
    __syncthreads();
    int excl = s - v + (w > 0 ? ws[0] : 0);
    g_blockoff[t] = excl;
    if (t == 63) g_rowstart[NN] = excl + v;
}

__global__ void scan3_kernel() {   // 64 blocks x 256 threads
    int i = blockIdx.x * 256 + threadIdx.x;
    int v = g_rowstart[i] + g_blockoff[blockIdx.x];
    g_rowstart[i] = v;
    g_cursor[i] = v;
}

__global__ void fill_kernel(const int* __restrict__ src, const int* __restrict__ dst, int E) {
    int e = blockIdx.x * blockDim.x + threadIdx.x;
    if (e >= E) return;
    int s = src[e], d = dst[e];
    int p = atomicAdd(&g_cursor[d], 1);
    g_csrc[p] = s;
    g_cw[p] = g_dinv[s] * g_dinv[d];
}

__global__ void transpose_fc1_kernel(const float* __restrict__ fc1w) {
    int idx = blockIdx.x * blockDim.x + threadIdx.x;
    if (idx < 64 * 256) {
        int j = idx >> 8, k = idx & 255;
        g_fc1wT[k * 64 + j] = fc1w[idx];
    }
}

// ---------------- GEMM with fused epilogue ----------------------------------
// ACT: 0 = plain store, 1 = +bias, 2 = +bias then relu
template <int ACT>
__global__ void gemm_kernel(const float* __restrict__ A, const float* __restrict__ B,
                            float* __restrict__ C, const float* __restrict__ bias,
                            int M, int K, int Nc) {
    __shared__ float As[64][17];
    __shared__ float Bs[16][64];
    const int tid = threadIdx.x;
    const int tx = tid & 15, ty = tid >> 4;
    const int rowBase = blockIdx.y * 64;
    const int colBase = blockIdx.x * 64;

    float acc[4][4];
#pragma unroll
    for (int i = 0; i < 4; i++)
#pragma unroll
        for (int j = 0; j < 4; j++) acc[i][j] = 0.0f;

    for (int k0 = 0; k0 < K; k0 += 16) {
#pragma unroll
        for (int l = 0; l < 4; l++) {
            int i = tid + l * 256;
            int r = i >> 4, c = i & 15;
            As[r][c] = A[(size_t)(rowBase + r) * K + k0 + c];
        }
#pragma unroll
        for (int l = 0; l < 4; l++) {
            int i = tid + l * 256;
            int r = i >> 6, c = i & 63;
            Bs[r][c] = B[(size_t)(k0 + r) * Nc + colBase + c];
        }
        __syncthreads();
#pragma unroll
        for (int kk = 0; kk < 16; kk++) {
            float a[4], b[4];
#pragma unroll
            for (int i = 0; i < 4; i++) a[i] = As[ty * 4 + i][kk];
#pragma unroll
            for (int j = 0; j < 4; j++) b[j] = Bs[kk][tx * 4 + j];
#pragma unroll
            for (int i = 0; i < 4; i++)
#pragma unroll
                for (int j = 0; j < 4; j++) acc[i][j] = fmaf(a[i], b[j], acc[i][j]);
        }
        __syncthreads();
    }
    float bv[4];
    if (ACT > 0) {
#pragma unroll
        for (int j = 0; j < 4; j++) bv[j] = bias[colBase + tx * 4 + j];
    }
#pragma unroll
    for (int i = 0; i < 4; i++) {
        int r = rowBase + ty * 4 + i;
#pragma unroll
        for (int j = 0; j < 4; j++) {
            float v = acc[i][j];
            if (ACT > 0) v += bv[j];
            if (ACT == 2) v = fmaxf(v, 0.0f);
            C[(size_t)r * Nc + colBase + tx * 4 + j] = v;
        }
    }
}

// ---------------- gather aggregation in 128-dim input space -----------------
// one warp per node (32 float4 = 128 floats), 8 nodes per 256-thread block
__global__ void gather128_kernel(const float* __restrict__ X, float* __restrict__ out) {
    const int node = blockIdx.x * 8 + (threadIdx.x >> 5);
    const int t = threadIdx.x & 31;
    const float di = g_dinv[node];
    float4 acc = ((const float4*)X)[node * 32 + t];
    const float w0 = di * di;
    acc.x *= w0; acc.y *= w0; acc.z *= w0; acc.w *= w0;

    int k = g_rowstart[node];
    const int end = g_rowstart[node + 1];
    for (; k + 2 <= end; k += 2) {
        int s0 = g_csrc[k];
        int s1 = g_csrc[k + 1];
        float wa = g_cw[k], wb = g_cw[k + 1];
        float4 v0 = ((const float4*)X)[s0 * 32 + t];
        float4 v1 = ((const float4*)X)[s1 * 32 + t];
        acc.x = fmaf(wa, v0.x, acc.x); acc.y = fmaf(wa, v0.y, acc.y);
        acc.z = fmaf(wa, v0.z, acc.z); acc.w = fmaf(wa, v0.w, acc.w);
        acc.x = fmaf(wb, v1.x, acc.x); acc.y = fmaf(wb, v1.y, acc.y);
        acc.z = fmaf(wb, v1.z, acc.z); acc.w = fmaf(wb, v1.w, acc.w);
    }
    if (k < end) {
        int s0 = g_csrc[k];
        float wa = g_cw[k];
        float4 v0 = ((const float4*)X)[s0 * 32 + t];
        acc.x = fmaf(wa, v0.x, acc.x); acc.y = fmaf(wa, v0.y, acc.y);
        acc.z = fmaf(wa, v0.z, acc.z); acc.w = fmaf(wa, v0.w, acc.w);
    }
    ((float4*)out)[node * 32 + t] = acc;
}

// ---------------- gather aggregation 256-dim, fused bias --------------------
// one 64-thread block per node
__global__ void gather256_kernel(const float* __restrict__ xw, const float* __restrict__ bias,
                                 float* __restrict__ out) {
    const int i = blockIdx.x;
    const int t = threadIdx.x;   // 0..63
    const float di = g_dinv[i];
    float4 acc = ((const float4*)xw)[i * 64 + t];
    const float w0 = di * di;
    acc.x *= w0; acc.y *= w0; acc.z *= w0; acc.w *= w0;

    int k = g_rowstart[i];
    const int end = g_rowstart[i + 1];
    for (; k + 2 <= end; k += 2) {
        int s0 = g_csrc[k];
        int s1 = g_csrc[k + 1];
        float wa = g_cw[k], wb = g_cw[k + 1];
        float4 v0 = ((const float4*)xw)[s0 * 64 + t];
        float4 v1 = ((const float4*)xw)[s1 * 64 + t];
        acc.x = fmaf(wa, v0.x, acc.x); acc.y = fmaf(wa, v0.y, acc.y);
        acc.z = fmaf(wa, v0.z, acc.z); acc.w = fmaf(wa, v0.w, acc.w);
        acc.x = fmaf(wb, v1.x, acc.x); acc.y = fmaf(wb, v1.y, acc.y);
        acc.z = fmaf(wb, v1.z, acc.z); acc.w = fmaf(wb, v1.w, acc.w);
    }
    if (k < end) {
        int s0 = g_csrc[k];
        float wa = g_cw[k];
        float4 v0 = ((const float4*)xw)[s0 * 64 + t];
        acc.x = fmaf(wa, v0.x, acc.x); acc.y = fmaf(wa, v0.y, acc.y);
        acc.z = fmaf(wa, v0.z, acc.z); acc.w = fmaf(wa, v0.w, acc.w);
    }
    float4 b = ((const float4*)bias)[t];
    acc.x += b.x; acc.y += b.y; acc.z += b.z; acc.w += b.w;
    ((float4*)out)[i * 64 + t] = acc;
}

// ---------------- assignment MLP: 4 nodes/block, 64 threads -----------------
__global__ void mlp_kernel(const float* __restrict__ h2,
                           const float* __restrict__ fc1b,
                           const float* __restrict__ fc2w, const float* __restrict__ fc2b) {
    __shared__ float s_row[4][256];
    __shared__ float s_a1[4][64];
    __shared__ float s_logit[4][2];
    const int t = threadIdx.x;      // 0..63
    const int i0 = blockIdx.x * 4;

#pragma unroll
    for (int l = 0; l < 4; l++) {
        int idx = t + l * 64;
        float4 v = ((const float4*)(h2 + (size_t)i0 * 256))[idx];
        ((float4*)&s_row[0][0])[idx] = v;
    }
    __syncthreads();

    float a0 = 0.f, a1 = 0.f, a2 = 0.f, a3 = 0.f;
#pragma unroll 4
    for (int kk = 0; kk < 256; kk++) {
        float wv = g_fc1wT[kk * 64 + t];
        a0 = fmaf(s_row[0][kk], wv, a0);
        a1 = fmaf(s_row[1][kk], wv, a1);
        a2 = fmaf(s_row[2][kk], wv, a2);
        a3 = fmaf(s_row[3][kk], wv, a3);
    }
    const float bb = fc1b[t];
    s_a1[0][t] = tanhf(a0 + bb);
    s_a1[1][t] = tanhf(a1 + bb);
    s_a1[2][t] = tanhf(a2 + bb);
    s_a1[3][t] = tanhf(a3 + bb);
    __syncthreads();

    if (t < 8) {
        int node = t >> 1, j = t & 1;
        float l = fc2b[j];
        const float* w2 = fc2w + j * 64;
#pragma unroll
        for (int kk = 0; kk < 64; kk++) l = fmaf(s_a1[node][kk], w2[kk], l);
        s_logit[node][j] = l;
    }
    __syncthreads();
    if (t < 4) {
        float l0 = s_logit[t][0], l1 = s_logit[t][1];
        float m = fmaxf(l0, l1);
        float e0 = __expf(l0 - m), e1 = __expf(l1 - m);
        float inv = 1.0f / (e0 + e1);
        g_assign[(i0 + t) * 2 + 0] = e0 * inv;
        g_assign[(i0 + t) * 2 + 1] = e1 * inv;
    }
}

// ---------------- pooled reductions ------------------------------------------
__global__ void group_kernel(const float* __restrict__ h2, int n) {
    int t = threadIdx.x;   // 256
    float acc0 = 0.0f, acc1 = 0.0f;
    for (int i = blockIdx.x; i < n; i += gridDim.x) {
        float a0 = g_assign[i * 2], a1 = g_assign[i * 2 + 1];
        float v = h2[(size_t)i * 256 + t];
        acc0 = fmaf(a0, v, acc0);
        acc1 = fmaf(a1, v, acc1);
    }
    atomicAdd(&g_group[t], acc0);
    atomicAdd(&g_group[256 + t], acc1);
}

__global__ void newadj_kernel(const int* __restrict__ src, const int* __restrict__ dst, int E) {
    float s00 = 0, s01 = 0, s10 = 0, s11 = 0;
    for (int e = blockIdx.x * blockDim.x + threadIdx.x; e < E; e += gridDim.x * blockDim.x) {
        int s = src[e], d = dst[e];
        float as0 = g_assign[s * 2], as1 = g_assign[s * 2 + 1];
        float ad0 = g_assign[d * 2], ad1 = g_assign[d * 2 + 1];
        s00 = fmaf(as0, ad0, s00);
        s01 = fmaf(as0, ad1, s01);
        s10 = fmaf(as1, ad0, s10);
        s11 = fmaf(as1, ad1, s11);
    }
#pragma unroll
    for (int off = 16; off > 0; off >>= 1) {
        s00 += __shfl_down_sync(0xffffffffu, s00, off);
        s01 += __shfl_down_sync(0xffffffffu, s01, off);
        s10 += __shfl_down_sync(0xffffffffu, s10, off);
        s11 += __shfl_down_sync(0xffffffffu, s11, off);
    }
    __shared__ float sh[4][8];
    int lane = threadIdx.x & 31, w = threadIdx.x >> 5;
    if (lane == 0) { sh[0][w] = s00; sh[1][w] = s01; sh[2][w] = s10; sh[3][w] = s11; }
    __syncthreads();
    if (threadIdx.x < 4) {
        float sum = 0;
        int nw = blockDim.x >> 5;
        for (int k = 0; k < nw; k++) sum += sh[threadIdx.x][k];
        atomicAdd(&g_newadj[threadIdx.x], sum);
    }
}

__global__ void final_kernel(float* __restrict__ out) {
    int t = threadIdx.x;   // 256
    float g0 = g_group[t], g1 = g_group[256 + t];
    out[t]        = 0.5f * (g0 + g1);
    out[256 + t]  = fminf(fmaxf(g0, -100.0f), 100.0f);
    out[512 + t]  = fminf(fmaxf(g1, -100.0f), 100.0f);
    if (t == 0) {
        float n00 = g_newadj[0], n01 = g_newadj[1];
        float n10 = g_newadj[2], n11 = g_newadj[3];
        float d0 = fmaxf(fabsf(n00) + fabsf(n01), 1e-12f);
        float d1 = fmaxf(fabsf(n10) + fabsf(n11), 1e-12f);
        float diag0 = n00 / d0 - 1.0f;
        float diag1 = n11 / d1 - 1.0f;
        out[768] = 0.5f * (diag0 * diag0 + diag1 * diag1);
    }
}

// ---------------- launch ------------------------------------------------------

extern "C" void kernel_launch(void* const* d_in, const int* in_sizes, int n_in,
                              void* d_out, int out_size) {
    const float* features = (const float*)d_in[0];
    const int*   edges    = (const int*)d_in[1];
    const float* W1   = (const float*)d_in[2];
    const float* b1   = (const float*)d_in[3];
    const float* W2   = (const float*)d_in[4];
    const float* b2   = (const float*)d_in[5];
    const float* fc1w = (const float*)d_in[6];
    const float* fc1b = (const float*)d_in[7];
    const float* fc2w = (const float*)d_in[8];
    const float* fc2b = (const float*)d_in[9];
    float* out = (float*)d_out;

    const int n = in_sizes[0] / F_IN;       // 16384
    const int E = in_sizes[1] / 2;          // 524288
    const int* src = edges;
    const int* dst = edges + E;

    float *aggX, *xw, *bufA, *bufB;
    cudaGetSymbolAddress((void**)&aggX, g_aggX);
    cudaGetSymbolAddress((void**)&xw,   g_xw);
    cudaGetSymbolAddress((void**)&bufA, g_bufA);
    cudaGetSymbolAddress((void**)&bufB, g_bufB);

    // ---- graph preprocessing: degrees, dinv, CSR-by-dst
    zero_kernel<<<(NN + 255) / 256, 256>>>();
    deg_kernel<<<(E + 255) / 256, 256>>>(dst, E);
    dinv_kernel<<<(n + 255) / 256, 256>>>(n);
    scan1_kernel<<<64, 256>>>();
    scan2_kernel<<<1, 64>>>();
    scan3_kernel<<<64, 256>>>();
    fill_kernel<<<(E + 255) / 256, 256>>>(src, dst, E);
    transpose_fc1_kernel<<<(64 * 256 + 255) / 256, 256>>>(fc1w);

    // ---- layer 1: relu((agg X) W1 + b1)   [aggregate-first: agg is linear]
    gather128_kernel<<<n / 8, 256>>>(features, aggX);
    {
        dim3 grid(H1 / 64, n / 64);
        gemm_kernel<2><<<grid, 256>>>(aggX, W1, bufA, b1, n, F_IN, H1);
    }

    // ---- layer 2: agg(h1 W2) + b2
    {
        dim3 grid(H2 / 64, n / 64);
        gemm_kernel<0><<<grid, 256>>>(bufA, W2, xw, nullptr, n, H1, H2);
    }
    gather256_kernel<<<n, 64>>>(xw, b2, bufB);

    // ---- assignment MLP + softmax
    mlp_kernel<<<n / 4, 64>>>(bufB, fc1b, fc2w, fc2b);

    // ---- pooled reductions
    group_kernel<<<256, 256>>>(bufB, n);
    newadj_kernel<<<256, 256>>>(src, dst, E);

    final_kernel<<<1, 256>>>(out);
}

// round 4
// speedup vs baseline: 8.0233x; 1.2461x over previous
#include <cuda_runtime.h>
#include <cuda_bf16.h>
#include <math.h>

#define NN    16384
#define EE    524288
#define F_IN  128
#define H1    256
#define H2    256
#define D1    64

// ---------------- scratch (device globals) ----------------------------------
__device__ int   g_degi[NN];
__device__ int   g_rowstart[NN + 1];
__device__ int   g_blocksum[64];
__device__ int   g_blockoff[64];
__device__ int   g_cursor[NN];
__device__ int   g_csrc[EE];
__device__ float g_cw[EE];
__device__ float g_dinv[NN];
__device__ float g_fc1wT[256 * 64];
__device__ float g_aggX[NN * F_IN];
__device__ float g_xw  [NN * 256];
__device__ float g_bufA[NN * 256];    // h1
__device__ float g_bufB[NN * 256];    // h2
__device__ float g_assign[NN * 2];
__device__ float g_group[2 * 256];
__device__ float g_newadj[4];

// ---------------- setup kernels ---------------------------------------------

// zero + fc1 transpose fused (grid 64 x 256 = 16384 threads)
__global__ void zero_kernel(const float* __restrict__ fc1w) {
    int i = blockIdx.x * blockDim.x + threadIdx.x;
    g_degi[i] = 0;
    if (i < 512) g_group[i] = 0.0f;
    if (i < 4)   g_newadj[i] = 0.0f;
    // fc1w is [64][256]; write transposed [256][64]
    int j = i >> 8, k = i & 255;
    g_fc1wT[k * 64 + j] = fc1w[i];
}

__global__ void deg_kernel(const int* __restrict__ dst, int E) {
    int e = blockIdx.x * blockDim.x + threadIdx.x;
    if (e < E) atomicAdd(&g_degi[dst[e]], 1);
}

// scan phase 1 + dinv fused
__global__ void scan1_kernel() {   // 64 blocks x 256 threads
    const int b = blockIdx.x, t = threadIdx.x;
    const int lane = t & 31, w = t >> 5;
    int v = g_degi[b * 256 + t];
    g_dinv[b * 256 + t] = rsqrtf((float)v + 1.0f);   // +1 self loop
    int s = v;
#pragma unroll
    for (int off = 1; off < 32; off <<= 1) {
        int u = __shfl_up_sync(0xffffffffu, s, off);
        if (lane >= off) s += u;
    }
    __shared__ int ws[8];
    if (lane == 31) ws[w] = s;
    __syncthreads();
    if (t < 8) {
        int x = ws[t];
#pragma unroll
        for (int off = 1; off < 8; off <<= 1) {
            int u = __shfl_up_sync(0xffu, x, off);
            if (t >= off) x += u;
        }
        ws[t] = x;
    }
    __syncthreads();
    int excl = s - v + (w > 0 ? ws[w - 1] : 0);
    g_rowstart[b * 256 + t] = excl;
    if (t == 255) g_blocksum[b] = excl + v;
}

__global__ void scan2_kernel() {   // 1 block x 64 threads
    int t = threadIdx.x;
    int v = g_blocksum[t];
    int s = v;
    int lane = t & 31, w = t >> 5;
#pragma unroll
    for (int off = 1; off < 32; off <<= 1) {
        int u = __shfl_up_sync(0xffffffffu, s, off);
        if (lane >= off) s += u;
    }
    __shared__ int ws[2];
    if (lane == 31) ws[w] = s;
    __syncthreads();
    int excl = s - v + (w > 0 ? ws[0] : 0);
    g_blockoff[t] = excl;
    if (t == 63) g_rowstart[NN] = excl + v;
}

__global__ void scan3_kernel() {   // 64 blocks x 256 threads
    int i = blockIdx.x * 256 + threadIdx.x;
    int v = g_rowstart[i] + g_blockoff[blockIdx.x];
    g_rowstart[i] = v;
    g_cursor[i] = v;
}

__global__ void fill_kernel(const int* __restrict__ src, const int* __restrict__ dst, int E) {
    int e = blockIdx.x * blockDim.x + threadIdx.x;
    if (e >= E) return;
    int s = src[e], d = dst[e];
    int p = atomicAdd(&g_cursor[d], 1);
    g_csrc[p] = s;
    g_cw[p] = g_dinv[s] * g_dinv[d];
}

// ---------------- SGEMM: 128x128 block, 8x8 per thread, double-buffered -----
// ACT: 0 = plain store, 2 = +bias then relu
template <int ACT>
__global__ void __launch_bounds__(256, 2)
sgemm_kernel(const float* __restrict__ A, const float* __restrict__ B,
             float* __restrict__ C, const float* __restrict__ bias,
             int M, int K, int Nc) {
    __shared__ float As[2][8][128];
    __shared__ float Bs[2][8][128];
    const int tid = threadIdx.x;
    const int tx = tid & 15, ty = tid >> 4;
    const int rowBase = blockIdx.y * 128;
    const int colBase = blockIdx.x * 128;

    const int ar = tid >> 1;            // 0..127
    const int ac = (tid & 1) * 4;       // 0 or 4
    const int bk = tid >> 5;            // 0..7
    const int bn = (tid & 31) * 4;      // 0..124

    const float* Aptr = A + (size_t)(rowBase + ar) * K + ac;
    const float* Bptr = B + (size_t)bk * Nc + colBase + bn;

    float4 av = *(const float4*)Aptr;
    float4 bv = *(const float4*)Bptr;

    float acc[8][8];
#pragma unroll
    for (int i = 0; i < 8; i++)
#pragma unroll
        for (int j = 0; j < 8; j++) acc[i][j] = 0.0f;

    int buf = 0;
    As[buf][ac + 0][ar] = av.x;
    As[buf][ac + 1][ar] = av.y;
    As[buf][ac + 2][ar] = av.z;
    As[buf][ac + 3][ar] = av.w;
    *(float4*)&Bs[buf][bk][bn] = bv;
    __syncthreads();

    for (int k0 = 8; k0 <= K; k0 += 8) {
        if (k0 < K) {
            av = *(const float4*)(Aptr + k0);
            bv = *(const float4*)(Bptr + (size_t)k0 * Nc);
        }
#pragma unroll
        for (int kk = 0; kk < 8; kk++) {
            float a[8], b[8];
            *(float4*)&a[0] = *(const float4*)&As[buf][kk][ty * 4];
            *(float4*)&a[4] = *(const float4*)&As[buf][kk][64 + ty * 4];
            *(float4*)&b[0] = *(const float4*)&Bs[buf][kk][tx * 4];
            *(float4*)&b[4] = *(const float4*)&Bs[buf][kk][64 + tx * 4];
#pragma unroll
            for (int i = 0; i < 8; i++)
#pragma unroll
                for (int j = 0; j < 8; j++) acc[i][j] = fmaf(a[i], b[j], acc[i][j]);
        }
        if (k0 < K) {
            buf ^= 1;
            As[buf][ac + 0][ar] = av.x;
            As[buf][ac + 1][ar] = av.y;
            As[buf][ac + 2][ar] = av.z;
            As[buf][ac + 3][ar] = av.w;
            *(float4*)&Bs[buf][bk][bn] = bv;
            __syncthreads();
        }
    }

    float bv0[8];
    if (ACT > 0) {
#pragma unroll
        for (int j = 0; j < 8; j++) {
            int c = (j < 4) ? (tx * 4 + j) : (64 + tx * 4 + j - 4);
            bv0[j] = bias[colBase + c];
        }
    }
#pragma unroll
    for (int i = 0; i < 8; i++) {
        int r = rowBase + ((i < 4) ? (ty * 4 + i) : (64 + ty * 4 + i - 4));
        float* crow = C + (size_t)r * Nc + colBase;
        float4 v0, v1;
        float t0[8];
#pragma unroll
        for (int j = 0; j < 8; j++) {
            float v = acc[i][j];
            if (ACT > 0) v += bv0[j];
            if (ACT == 2) v = fmaxf(v, 0.0f);
            t0[j] = v;
        }
        v0 = make_float4(t0[0], t0[1], t0[2], t0[3]);
        v1 = make_float4(t0[4], t0[5], t0[6], t0[7]);
        *(float4*)(crow + tx * 4) = v0;
        *(float4*)(crow + 64 + tx * 4) = v1;
    }
}

// ---------------- gather aggregation in 128-dim input space -----------------
__global__ void gather128_kernel(const float* __restrict__ X, float* __restrict__ out) {
    const int node = blockIdx.x * 8 + (threadIdx.x >> 5);
    const int t = threadIdx.x & 31;
    const float di = g_dinv[node];
    float4 acc = ((const float4*)X)[node * 32 + t];
    const float w0 = di * di;
    acc.x *= w0; acc.y *= w0; acc.z *= w0; acc.w *= w0;

    int k = g_rowstart[node];
    const int end = g_rowstart[node + 1];
    for (; k + 2 <= end; k += 2) {
        int s0 = g_csrc[k];
        int s1 = g_csrc[k + 1];
        float wa = g_cw[k], wb = g_cw[k + 1];
        float4 v0 = ((const float4*)X)[s0 * 32 + t];
        float4 v1 = ((const float4*)X)[s1 * 32 + t];
        acc.x = fmaf(wa, v0.x, acc.x); acc.y = fmaf(wa, v0.y, acc.y);
        acc.z = fmaf(wa, v0.z, acc.z); acc.w = fmaf(wa, v0.w, acc.w);
        acc.x = fmaf(wb, v1.x, acc.x); acc.y = fmaf(wb, v1.y, acc.y);
        acc.z = fmaf(wb, v1.z, acc.z); acc.w = fmaf(wb, v1.w, acc.w);
    }
    if (k < end) {
        int s0 = g_csrc[k];
        float wa = g_cw[k];
        float4 v0 = ((const float4*)X)[s0 * 32 + t];
        acc.x = fmaf(wa, v0.x, acc.x); acc.y = fmaf(wa, v0.y, acc.y);
        acc.z = fmaf(wa, v0.z, acc.z); acc.w = fmaf(wa, v0.w, acc.w);
    }
    ((float4*)out)[node * 32 + t] = acc;
}

// ---------------- gather aggregation 256-dim, fused bias --------------------
__global__ void gather256_kernel(const float* __restrict__ xw, const float* __restrict__ bias,
                                 float* __restrict__ out) {
    const int i = blockIdx.x;
    const int t = threadIdx.x;   // 0..63
    const float di = g_dinv[i];
    float4 acc = ((const float4*)xw)[i * 64 + t];
    const float w0 = di * di;
    acc.x *= w0; acc.y *= w0; acc.z *= w0; acc.w *= w0;

    int k = g_rowstart[i];
    const int end = g_rowstart[i + 1];
    for (; k + 2 <= end; k += 2) {
        int s0 = g_csrc[k];
        int s1 = g_csrc[k + 1];
        float wa = g_cw[k], wb = g_cw[k + 1];
        float4 v0 = ((const float4*)xw)[s0 * 64 + t];
        float4 v1 = ((const float4*)xw)[s1 * 64 + t];
        acc.x = fmaf(wa, v0.x, acc.x); acc.y = fmaf(wa, v0.y, acc.y);
        acc.z = fmaf(wa, v0.z, acc.z); acc.w = fmaf(wa, v0.w, acc.w);
        acc.x = fmaf(wb, v1.x, acc.x); acc.y = fmaf(wb, v1.y, acc.y);
        acc.z = fmaf(wb, v1.z, acc.z); acc.w = fmaf(wb, v1.w, acc.w);
    }
    if (k < end) {
        int s0 = g_csrc[k];
        float wa = g_cw[k];
        float4 v0 = ((const float4*)xw)[s0 * 64 + t];
        acc.x = fmaf(wa, v0.x, acc.x); acc.y = fmaf(wa, v0.y, acc.y);
        acc.z = fmaf(wa, v0.z, acc.z); acc.w = fmaf(wa, v0.w, acc.w);
    }
    float4 b = ((const float4*)bias)[t];
    acc.x += b.x; acc.y += b.y; acc.z += b.z; acc.w += b.w;
    ((float4*)out)[i * 64 + t] = acc;
}

// ---------------- MLP + softmax + fused group reduction ---------------------
// 16 nodes per block, 256 threads. rows padded to 260 floats (bank-safe).
__global__ void mlp_kernel(const float* __restrict__ h2,
                           const float* __restrict__ fc1b,
                           const float* __restrict__ fc2w, const float* __restrict__ fc2b) {
    __shared__ float s_row[16][260];
    __shared__ float s_a1[16][64];
    __shared__ float s_asg[16][2];
    const int t = threadIdx.x;      // 0..255
    const int i0 = blockIdx.x * 16;

    // load 16 rows (16*256 floats = 1024 float4), 4 float4 per thread
#pragma unroll
    for (int l = 0; l < 4; l++) {
        int idx = t + l * 256;          // 0..1023
        int row = idx >> 6, c4 = idx & 63;
        float4 v = ((const float4*)(h2 + (size_t)i0 * 256))[idx];
        ((float4*)&s_row[row][0])[c4] = v;
    }
    __syncthreads();

    const int j = t & 63, g = t >> 6;   // thread handles nodes g, g+4, g+8, g+12
    float a0 = 0.f, a1 = 0.f, a2 = 0.f, a3 = 0.f;
#pragma unroll 4
    for (int k = 0; k < 256; k++) {
        float wv = g_fc1wT[k * 64 + j];
        a0 = fmaf(s_row[g][k],      wv, a0);
        a1 = fmaf(s_row[g + 4][k],  wv, a1);
        a2 = fmaf(s_row[g + 8][k],  wv, a2);
        a3 = fmaf(s_row[g + 12][k], wv, a3);
    }
    const float bb = fc1b[j];
    s_a1[g][j]      = tanhf(a0 + bb);
    s_a1[g + 4][j]  = tanhf(a1 + bb);
    s_a1[g + 8][j]  = tanhf(a2 + bb);
    s_a1[g + 12][j] = tanhf(a3 + bb);
    __syncthreads();

    if (t < 16) {
        float l0 = fc2b[0], l1 = fc2b[1];
#pragma unroll
        for (int k = 0; k < 64; k++) {
            float av = s_a1[t][k];
            l0 = fmaf(av, fc2w[k],      l0);
            l1 = fmaf(av, fc2w[64 + k], l1);
        }
        float m = fmaxf(l0, l1);
        float e0 = __expf(l0 - m), e1 = __expf(l1 - m);
        float inv = 1.0f / (e0 + e1);
        float p0 = e0 * inv, p1 = e1 * inv;
        s_asg[t][0] = p0; s_asg[t][1] = p1;
        g_assign[(i0 + t) * 2 + 0] = p0;
        g_assign[(i0 + t) * 2 + 1] = p1;
    }
    __syncthreads();

    // fused group partial: feature f = t (0..255)
    float p0 = 0.f, p1 = 0.f;
#pragma unroll
    for (int nd = 0; nd < 16; nd++) {
        float v = s_row[nd][t];
        p0 = fmaf(s_asg[nd][0], v, p0);
        p1 = fmaf(s_asg[nd][1], v, p1);
    }
    atomicAdd(&g_group[t], p0);
    atomicAdd(&g_group[256 + t], p1);
}

// ---------------- 2x2 pooled adjacency --------------------------------------
__global__ void newadj_kernel(const int* __restrict__ src, const int* __restrict__ dst, int E) {
    float s00 = 0, s01 = 0, s10 = 0, s11 = 0;
    for (int e = blockIdx.x * blockDim.x + threadIdx.x; e < E; e += gridDim.x * blockDim.x) {
        int s = src[e], d = dst[e];
        float as0 = g_assign[s * 2], as1 = g_assign[s * 2 + 1];
        float ad0 = g_assign[d * 2], ad1 = g_assign[d * 2 + 1];
        s00 = fmaf(as0, ad0, s00);
        s01 = fmaf(as0, ad1, s01);
        s10 = fmaf(as1, ad0, s10);
        s11 = fmaf(as1, ad1, s11);
    }
#pragma unroll
    for (int off = 16; off > 0; off >>= 1) {
        s00 += __shfl_down_sync(0xffffffffu, s00, off);
        s01 += __shfl_down_sync(0xffffffffu, s01, off);
        s10 += __shfl_down_sync(0xffffffffu, s10, off);
        s11 += __shfl_down_sync(0xffffffffu, s11, off);
    }
    __shared__ float sh[4][8];
    int lane = threadIdx.x & 31, w = threadIdx.x >> 5;
    if (lane == 0) { sh[0][w] = s00; sh[1][w] = s01; sh[2][w] = s10; sh[3][w] = s11; }
    __syncthreads();
    if (threadIdx.x < 4) {
        float sum = 0;
        int nw = blockDim.x >> 5;
        for (int k = 0; k < nw; k++) sum += sh[threadIdx.x][k];
        atomicAdd(&g_newadj[threadIdx.x], sum);
    }
}

__global__ void final_kernel(float* __restrict__ out) {
    int t = threadIdx.x;   // 256
    float g0 = g_group[t], g1 = g_group[256 + t];
    out[t]        = 0.5f * (g0 + g1);
    out[256 + t]  = fminf(fmaxf(g0, -100.0f), 100.0f);
    out[512 + t]  = fminf(fmaxf(g1, -100.0f), 100.0f);
    if (t == 0) {
        float n00 = g_newadj[0], n01 = g_newadj[1];
        float n10 = g_newadj[2], n11 = g_newadj[3];
        float d0 = fmaxf(fabsf(n00) + fabsf(n01), 1e-12f);
        float d1 = fmaxf(fabsf(n10) + fabsf(n11), 1e-12f);
        float diag0 = n00 / d0 - 1.0f;
        float diag1 = n11 / d1 - 1.0f;
        out[768] = 0.5f * (diag0 * diag0 + diag1 * diag1);
    }
}

// ---------------- launch ------------------------------------------------------

extern "C" void kernel_launch(void* const* d_in, const int* in_sizes, int n_in,
                              void* d_out, int out_size) {
    const float* features = (const float*)d_in[0];
    const int*   edges    = (const int*)d_in[1];
    const float* W1   = (const float*)d_in[2];
    const float* b1   = (const float*)d_in[3];
    const float* W2   = (const float*)d_in[4];
    const float* b2   = (const float*)d_in[5];
    const float* fc1w = (const float*)d_in[6];
    const float* fc1b = (const float*)d_in[7];
    const float* fc2w = (const float*)d_in[8];
    const float* fc2b = (const float*)d_in[9];
    float* out = (float*)d_out;

    const int n = in_sizes[0] / F_IN;       // 16384
    const int E = in_sizes[1] / 2;          // 524288
    const int* src = edges;
    const int* dst = edges + E;

    float *aggX, *xw, *bufA, *bufB;
    cudaGetSymbolAddress((void**)&aggX, g_aggX);
    cudaGetSymbolAddress((void**)&xw,   g_xw);
    cudaGetSymbolAddress((void**)&bufA, g_bufA);
    cudaGetSymbolAddress((void**)&bufB, g_bufB);

    // ---- graph preprocessing
    zero_kernel<<<64, 256>>>(fc1w);
    deg_kernel<<<(E + 255) / 256, 256>>>(dst, E);
    scan1_kernel<<<64, 256>>>();
    scan2_kernel<<<1, 64>>>();
    scan3_kernel<<<64, 256>>>();
    fill_kernel<<<(E + 255) / 256, 256>>>(src, dst, E);

    // ---- layer 1: relu((agg X) W1 + b1)
    gather128_kernel<<<n / 8, 256>>>(features, aggX);
    {
        dim3 grid(H1 / 128, n / 128);
        sgemm_kernel<2><<<grid, 256>>>(aggX, W1, bufA, b1, n, F_IN, H1);
    }

    // ---- layer 2: agg(h1 W2) + b2
    {
        dim3 grid(H2 / 128, n / 128);
        sgemm_kernel<0><<<grid, 256>>>(bufA, W2, xw, nullptr, n, H1, H2);
    }
    gather256_kernel<<<n, 64>>>(xw, b2, bufB);

    // ---- assignment MLP + softmax + group features (fused)
    mlp_kernel<<<n / 16, 256>>>(bufB, fc1b, fc2w, fc2b);

    // ---- 2x2 pooled adjacency
    newadj_kernel<<<256, 256>>>(src, dst, E);

    final_kernel<<<1, 256>>>(out);
}

// round 5
// speedup vs baseline: 8.6011x; 1.0720x over previous
#include <cuda_runtime.h>
#include <cuda_bf16.h>
#include <cuda_fp16.h>
#include <math.h>

#define NN    16384
#define EE    524288
#define F_IN  128
#define H1    256
#define H2    256
#define D1    64

// ---------------- scratch (device globals) ----------------------------------
__device__ int    g_degi[NN];
__device__ int    g_rowstart[NN + 1];
__device__ int    g_blocksum[64];
__device__ int    g_cursor[NN];
__device__ int    g_csrc[EE];
__device__ float  g_cw[EE];
__device__ float  g_dinv[NN];
__device__ float  g_fc1wT[256 * 64];
__device__ __half g_feath[NN * F_IN];   // fp16 features for gather1
__device__ __half g_xwh [NN * 256];     // fp16 h1*W2 for gather2
__device__ float  g_aggX[NN * F_IN];
__device__ float  g_bufA[NN * 256];     // h1
__device__ float  g_bufB[NN * 256];     // h2
__device__ float  g_assign[NN * 2];
__device__ float  g_group[2 * 256];
__device__ float  g_newadj[4];

// ---------------- setup: zero + fc1 transpose + feature->half (fused) -------
// grid 2048 x 256 = 524288 threads (one per float4 of features)
__global__ void zero_kernel(const float* __restrict__ fc1w, const float* __restrict__ feat) {
    int i = blockIdx.x * blockDim.x + threadIdx.x;   // 0..524287
    if (i < NN)  g_degi[i] = 0;
    if (i < 512) g_group[i] = 0.0f;
    if (i < 4)   g_newadj[i] = 0.0f;
    if (i == 0)  g_rowstart[NN] = EE;
    if (i < 64 * 256) {
        int j = i >> 8, k = i & 255;
        g_fc1wT[k * 64 + j] = fc1w[i];
    }
    // convert 4 features to half
    float4 v = ((const float4*)feat)[i];
    __half2 h0 = __floats2half2_rn(v.x, v.y);
    __half2 h1 = __floats2half2_rn(v.z, v.w);
    uint2 u;
    u.x = *reinterpret_cast<unsigned int*>(&h0);
    u.y = *reinterpret_cast<unsigned int*>(&h1);
    ((uint2*)g_feath)[i] = u;
}

__global__ void deg_kernel(const int* __restrict__ dst, int E) {
    int e = blockIdx.x * blockDim.x + threadIdx.x;
    if (e < E) atomicAdd(&g_degi[dst[e]], 1);
}

// scan phase 1 + dinv fused (64 blocks x 256)
__global__ void scan1_kernel() {
    const int b = blockIdx.x, t = threadIdx.x;
    const int lane = t & 31, w = t >> 5;
    int v = g_degi[b * 256 + t];
    g_dinv[b * 256 + t] = rsqrtf((float)v + 1.0f);   // +1 self loop
    int s = v;
#pragma unroll
    for (int off = 1; off < 32; off <<= 1) {
        int u = __shfl_up_sync(0xffffffffu, s, off);
        if (lane >= off) s += u;
    }
    __shared__ int ws[8];
    if (lane == 31) ws[w] = s;
    __syncthreads();
    if (t < 8) {
        int x = ws[t];
#pragma unroll
        for (int off = 1; off < 8; off <<= 1) {
            int u = __shfl_up_sync(0xffu, x, off);
            if (t >= off) x += u;
        }
        ws[t] = x;
    }
    __syncthreads();
    int excl = s - v + (w > 0 ? ws[w - 1] : 0);
    g_rowstart[b * 256 + t] = excl;
    if (t == 255) g_blocksum[b] = excl + v;
}

// scan phase 2+3 fused: each block reduces its own offset from the 64 sums
__global__ void scan_off_kernel() {   // 64 blocks x 256 threads
    __shared__ int s_off;
    const int t = threadIdx.x, b = blockIdx.x;
    // threads 0..63: blocksum[t] if t < b else 0; reduce across 2 warps
    int v = (t < 64 && t < b) ? g_blocksum[t] : 0;
    if (t < 64) {
#pragma unroll
        for (int off = 16; off > 0; off >>= 1)
            v += __shfl_down_sync(0xffffffffu, v, off);
    }
    __shared__ int ws[2];
    if (t == 0)  ws[0] = v;
    if (t == 32) ws[1] = v;
    __syncthreads();
    if (t == 0) s_off = ws[0] + ws[1];
    __syncthreads();
    int i = b * 256 + t;
    int r = g_rowstart[i] + s_off;
    g_rowstart[i] = r;
    g_cursor[i] = r;
}

__global__ void fill_kernel(const int* __restrict__ src, const int* __restrict__ dst, int E) {
    int e = blockIdx.x * blockDim.x + threadIdx.x;
    if (e >= E) return;
    int s = src[e], d = dst[e];
    int p = atomicAdd(&g_cursor[d], 1);
    g_csrc[p] = s;
    g_cw[p] = g_dinv[s] * g_dinv[d];
}

// ---------------- SGEMM: 128x128 block, 8x8 per thread, double-buffered -----
// ACT: 0 = plain, 2 = +bias then relu.  HALF_OUT: store C as __half.
template <int ACT, bool HALF_OUT>
__global__ void __launch_bounds__(256, 2)
sgemm_kernel(const float* __restrict__ A, const float* __restrict__ B,
             void* __restrict__ Cv, const float* __restrict__ bias,
             int M, int K, int Nc) {
    __shared__ float As[2][8][128];
    __shared__ float Bs[2][8][128];
    const int tid = threadIdx.x;
    const int tx = tid & 15, ty = tid >> 4;
    const int rowBase = blockIdx.y * 128;
    const int colBase = blockIdx.x * 128;

    const int ar = tid >> 1;
    const int ac = (tid & 1) * 4;
    const int bk = tid >> 5;
    const int bn = (tid & 31) * 4;

    const float* Aptr = A + (size_t)(rowBase + ar) * K + ac;
    const float* Bptr = B + (size_t)bk * Nc + colBase + bn;

    float4 av = *(const float4*)Aptr;
    float4 bv = *(const float4*)Bptr;

    float acc[8][8];
#pragma unroll
    for (int i = 0; i < 8; i++)
#pragma unroll
        for (int j = 0; j < 8; j++) acc[i][j] = 0.0f;

    int buf = 0;
    As[buf][ac + 0][ar] = av.x;
    As[buf][ac + 1][ar] = av.y;
    As[buf][ac + 2][ar] = av.z;
    As[buf][ac + 3][ar] = av.w;
    *(float4*)&Bs[buf][bk][bn] = bv;
    __syncthreads();

    for (int k0 = 8; k0 <= K; k0 += 8) {
        if (k0 < K) {
            av = *(const float4*)(Aptr + k0);
            bv = *(const float4*)(Bptr + (size_t)k0 * Nc);
        }
#pragma unroll
        for (int kk = 0; kk < 8; kk++) {
            float a[8], b[8];
            *(float4*)&a[0] = *(const float4*)&As[buf][kk][ty * 4];
            *(float4*)&a[4] = *(const float4*)&As[buf][kk][64 + ty * 4];
            *(float4*)&b[0] = *(const float4*)&Bs[buf][kk][tx * 4];
            *(float4*)&b[4] = *(const float4*)&Bs[buf][kk][64 + tx * 4];
#pragma unroll
            for (int i = 0; i < 8; i++)
#pragma unroll
                for (int j = 0; j < 8; j++) acc[i][j] = fmaf(a[i], b[j], acc[i][j]);
        }
        if (k0 < K) {
            buf ^= 1;
            As[buf][ac + 0][ar] = av.x;
            As[buf][ac + 1][ar] = av.y;
            As[buf][ac + 2][ar] = av.z;
            As[buf][ac + 3][ar] = av.w;
            *(float4*)&Bs[buf][bk][bn] = bv;
            __syncthreads();
        }
    }

    float bv0[8];
    if (ACT > 0) {
#pragma unroll
        for (int j = 0; j < 8; j++) {
            int c = (j < 4) ? (tx * 4 + j) : (64 + tx * 4 + j - 4);
            bv0[j] = bias[colBase + c];
        }
    }
#pragma unroll
    for (int i = 0; i < 8; i++) {
        int r = rowBase + ((i < 4) ? (ty * 4 + i) : (64 + ty * 4 + i - 4));
        float t0[8];
#pragma unroll
        for (int j = 0; j < 8; j++) {
            float v = acc[i][j];
            if (ACT > 0) v += bv0[j];
            if (ACT == 2) v = fmaxf(v, 0.0f);
            t0[j] = v;
        }
        if (HALF_OUT) {
            __half* crow = (__half*)Cv + (size_t)r * Nc + colBase;
            __half2 h0 = __floats2half2_rn(t0[0], t0[1]);
            __half2 h1 = __floats2half2_rn(t0[2], t0[3]);
            __half2 h2 = __floats2half2_rn(t0[4], t0[5]);
            __half2 h3 = __floats2half2_rn(t0[6], t0[7]);
            uint2 u0, u1;
            u0.x = *reinterpret_cast<unsigned int*>(&h0);
            u0.y = *reinterpret_cast<unsigned int*>(&h1);
            u1.x = *reinterpret_cast<unsigned int*>(&h2);
            u1.y = *reinterpret_cast<unsigned int*>(&h3);
            *(uint2*)(crow + tx * 4) = u0;
            *(uint2*)(crow + 64 + tx * 4) = u1;
        } else {
            float* crow = (float*)Cv + (size_t)r * Nc + colBase;
            *(float4*)(crow + tx * 4) = make_float4(t0[0], t0[1], t0[2], t0[3]);
            *(float4*)(crow + 64 + tx * 4) = make_float4(t0[4], t0[5], t0[6], t0[7]);
        }
    }
}

// ---------------- gather aggregation, 128-dim, fp16 source ------------------
// one warp per node (32 lanes x 4 halves), 8 nodes per 256-thread block
__global__ void gather128h_kernel(float* __restrict__ out) {
    const int node = blockIdx.x * 8 + (threadIdx.x >> 5);
    const int t = threadIdx.x & 31;
    const uint2* X = (const uint2*)g_feath;

    const float di = g_dinv[node];
    const float w0 = di * di;
    uint2 u = X[node * 32 + t];
    float2 f0 = __half22float2(*(__half2*)&u.x);
    float2 f1 = __half22float2(*(__half2*)&u.y);
    float4 acc = make_float4(f0.x * w0, f0.y * w0, f1.x * w0, f1.y * w0);

    int k = g_rowstart[node];
    const int end = g_rowstart[node + 1];
    for (; k + 2 <= end; k += 2) {
        int s0 = g_csrc[k];
        int s1 = g_csrc[k + 1];
        float wa = g_cw[k], wb = g_cw[k + 1];
        uint2 ua = X[s0 * 32 + t];
        uint2 ub = X[s1 * 32 + t];
        float2 a0 = __half22float2(*(__half2*)&ua.x);
        float2 a1 = __half22float2(*(__half2*)&ua.y);
        float2 b0 = __half22float2(*(__half2*)&ub.x);
        float2 b1 = __half22float2(*(__half2*)&ub.y);
        acc.x = fmaf(wa, a0.x, acc.x); acc.y = fmaf(wa, a0.y, acc.y);
        acc.z = fmaf(wa, a1.x, acc.z); acc.w = fmaf(wa, a1.y, acc.w);
        acc.x = fmaf(wb, b0.x, acc.x); acc.y = fmaf(wb, b0.y, acc.y);
        acc.z = fmaf(wb, b1.x, acc.z); acc.w = fmaf(wb, b1.y, acc.w);
    }
    if (k < end) {
        int s0 = g_csrc[k];
        float wa = g_cw[k];
        uint2 ua = X[s0 * 32 + t];
        float2 a0 = __half22float2(*(__half2*)&ua.x);
        float2 a1 = __half22float2(*(__half2*)&ua.y);
        acc.x = fmaf(wa, a0.x, acc.x); acc.y = fmaf(wa, a0.y, acc.y);
        acc.z = fmaf(wa, a1.x, acc.z); acc.w = fmaf(wa, a1.y, acc.w);
    }
    ((float4*)out)[node * 32 + t] = acc;
}

// ---------------- gather aggregation, 256-dim, fp16 source, fused bias ------
// one 64-thread block per node (64 lanes x 4 halves)
__global__ void gather256h_kernel(const float* __restrict__ bias, float* __restrict__ out) {
    const int i = blockIdx.x;
    const int t = threadIdx.x;   // 0..63
    const uint2* X = (const uint2*)g_xwh;

    const float di = g_dinv[i];
    const float w0 = di * di;
    uint2 u = X[i * 64 + t];
    float2 f0 = __half22float2(*(__half2*)&u.x);
    float2 f1 = __half22float2(*(__half2*)&u.y);
    float4 acc = make_float4(f0.x * w0, f0.y * w0, f1.x * w0, f1.y * w0);

    int k = g_rowstart[i];
    const int end = g_rowstart[i + 1];
    for (; k + 2 <= end; k += 2) {
        int s0 = g_csrc[k];
        int s1 = g_csrc[k + 1];
        float wa = g_cw[k], wb = g_cw[k + 1];
        uint2 ua = X[s0 * 64 + t];
        uint2 ub = X[s1 * 64 + t];
        float2 a0 = __half22float2(*(__half2*)&ua.x);
        float2 a1 = __half22float2(*(__half2*)&ua.y);
        float2 b0 = __half22float2(*(__half2*)&ub.x);
        float2 b1 = __half22float2(*(__half2*)&ub.y);
        acc.x = fmaf(wa, a0.x, acc.x); acc.y = fmaf(wa, a0.y, acc.y);
        acc.z = fmaf(wa, a1.x, acc.z); acc.w = fmaf(wa, a1.y, acc.w);
        acc.x = fmaf(wb, b0.x, acc.x); acc.y = fmaf(wb, b0.y, acc.y);
        acc.z = fmaf(wb, b1.x, acc.z); acc.w = fmaf(wb, b1.y, acc.w);
    }
    if (k < end) {
        int s0 = g_csrc[k];
        float wa = g_cw[k];
        uint2 ua = X[s0 * 64 + t];
        float2 a0 = __half22float2(*(__half2*)&ua.x);
        float2 a1 = __half22float2(*(__half2*)&ua.y);
        acc.x = fmaf(wa, a0.x, acc.x); acc.y = fmaf(wa, a0.y, acc.y);
        acc.z = fmaf(wa, a1.x, acc.z); acc.w = fmaf(wa, a1.y, acc.w);
    }
    float4 b = ((const float4*)bias)[t];
    acc.x += b.x; acc.y += b.y; acc.z += b.z; acc.w += b.w;
    ((float4*)out)[i * 64 + t] = acc;
}

// ---------------- MLP + softmax + fused group reduction ---------------------
__global__ void mlp_kernel(const float* __restrict__ h2,
                           const float* __restrict__ fc1b,
                           const float* __restrict__ fc2w, const float* __restrict__ fc2b) {
    __shared__ float s_row[16][260];
    __shared__ float s_a1[16][64];
    __shared__ float s_asg[16][2];
    const int t = threadIdx.x;      // 0..255
    const int i0 = blockIdx.x * 16;

#pragma unroll
    for (int l = 0; l < 4; l++) {
        int idx = t + l * 256;
        int row = idx >> 6, c4 = idx & 63;
        float4 v = ((const float4*)(h2 + (size_t)i0 * 256))[idx];
        ((float4*)&s_row[row][0])[c4] = v;
    }
    __syncthreads();

    const int j = t & 63, g = t >> 6;
    float a0 = 0.f, a1 = 0.f, a2 = 0.f, a3 = 0.f;
#pragma unroll 4
    for (int k = 0; k < 256; k++) {
        float wv = g_fc1wT[k * 64 + j];
        a0 = fmaf(s_row[g][k],      wv, a0);
        a1 = fmaf(s_row[g + 4][k],  wv, a1);
        a2 = fmaf(s_row[g + 8][k],  wv, a2);
        a3 = fmaf(s_row[g + 12][k], wv, a3);
    }
    const float bb = fc1b[j];
    s_a1[g][j]      = tanhf(a0 + bb);
    s_a1[g + 4][j]  = tanhf(a1 + bb);
    s_a1[g + 8][j]  = tanhf(a2 + bb);
    s_a1[g + 12][j] = tanhf(a3 + bb);
    __syncthreads();

    if (t < 16) {
        float l0 = fc2b[0], l1 = fc2b[1];
#pragma unroll
        for (int k = 0; k < 64; k++) {
            float av = s_a1[t][k];
            l0 = fmaf(av, fc2w[k],      l0);
            l1 = fmaf(av, fc2w[64 + k], l1);
        }
        float m = fmaxf(l0, l1);
        float e0 = __expf(l0 - m), e1 = __expf(l1 - m);
        float inv = 1.0f / (e0 + e1);
        float p0 = e0 * inv, p1 = e1 * inv;
        s_asg[t][0] = p0; s_asg[t][1] = p1;
        g_assign[(i0 + t) * 2 + 0] = p0;
        g_assign[(i0 + t) * 2 + 1] = p1;
    }
    __syncthreads();

    float p0 = 0.f, p1 = 0.f;
#pragma unroll
    for (int nd = 0; nd < 16; nd++) {
        float v = s_row[nd][t];
        p0 = fmaf(s_asg[nd][0], v, p0);
        p1 = fmaf(s_asg[nd][1], v, p1);
    }
    atomicAdd(&g_group[t], p0);
    atomicAdd(&g_group[256 + t], p1);
}

// ---------------- 2x2 pooled adjacency --------------------------------------
__global__ void newadj_kernel(const int* __restrict__ src, const int* __restrict__ dst, int E) {
    float s00 = 0, s01 = 0, s10 = 0, s11 = 0;
    for (int e = blockIdx.x * blockDim.x + threadIdx.x; e < E; e += gridDim.x * blockDim.x) {
        int s = src[e], d = dst[e];
        float as0 = g_assign[s * 2], as1 = g_assign[s * 2 + 1];
        float ad0 = g_assign[d * 2], ad1 = g_assign[d * 2 + 1];
        s00 = fmaf(as0, ad0, s00);
        s01 = fmaf(as0, ad1, s01);
        s10 = fmaf(as1, ad0, s10);
        s11 = fmaf(as1, ad1, s11);
    }
#pragma unroll
    for (int off = 16; off > 0; off >>= 1) {
        s00 += __shfl_down_sync(0xffffffffu, s00, off);
        s01 += __shfl_down_sync(0xffffffffu, s01, off);
        s10 += __shfl_down_sync(0xffffffffu, s10, off);
        s11 += __shfl_down_sync(0xffffffffu, s11, off);
    }
    __shared__ float sh[4][8];
    int lane = threadIdx.x & 31, w = threadIdx.x >> 5;
    if (lane == 0) { sh[0][w] = s00; sh[1][w] = s01; sh[2][w] = s10; sh[3][w] = s11; }
    __syncthreads();
    if (threadIdx.x < 4) {
        float sum = 0;
        int nw = blockDim.x >> 5;
        for (int k = 0; k < nw; k++) sum += sh[threadIdx.x][k];
        atomicAdd(&g_newadj[threadIdx.x], sum);
    }
}

__global__ void final_kernel(float* __restrict__ out) {
    int t = threadIdx.x;   // 256
    float g0 = g_group[t], g1 = g_group[256 + t];
    out[t]        = 0.5f * (g0 + g1);
    out[256 + t]  = fminf(fmaxf(g0, -100.0f), 100.0f);
    out[512 + t]  = fminf(fmaxf(g1, -100.0f), 100.0f);
    if (t == 0) {
        float n00 = g_newadj[0], n01 = g_newadj[1];
        float n10 = g_newadj[2], n11 = g_newadj[3];
        float d0 = fmaxf(fabsf(n00) + fabsf(n01), 1e-12f);
        float d1 = fmaxf(fabsf(n10) + fabsf(n11), 1e-12f);
        float diag0 = n00 / d0 - 1.0f;
        float diag1 = n11 / d1 - 1.0f;
        out[768] = 0.5f * (diag0 * diag0 + diag1 * diag1);
    }
}

// ---------------- launch ------------------------------------------------------

extern "C" void kernel_launch(void* const* d_in, const int* in_sizes, int n_in,
                              void* d_out, int out_size) {
    const float* features = (const float*)d_in[0];
    const int*   edges    = (const int*)d_in[1];
    const float* W1   = (const float*)d_in[2];
    const float* b1   = (const float*)d_in[3];
    const float* W2   = (const float*)d_in[4];
    const float* b2   = (const float*)d_in[5];
    const float* fc1w = (const float*)d_in[6];
    const float* fc1b = (const float*)d_in[7];
    const float* fc2w = (const float*)d_in[8];
    const float* fc2b = (const float*)d_in[9];
    float* out = (float*)d_out;

    const int n = in_sizes[0] / F_IN;       // 16384
    const int E = in_sizes[1] / 2;          // 524288
    const int* src = edges;
    const int* dst = edges + E;

    float *aggX, *bufA, *bufB;
    __half* xwh;
    cudaGetSymbolAddress((void**)&aggX, g_aggX);
    cudaGetSymbolAddress((void**)&bufA, g_bufA);
    cudaGetSymbolAddress((void**)&bufB, g_bufB);
    cudaGetSymbolAddress((void**)&xwh,  g_xwh);

    // ---- preprocessing: zero + transpose + feat->half, degrees, scan, CSR
    zero_kernel<<<(n * F_IN / 4 + 255) / 256, 256>>>(fc1w, features);
    deg_kernel<<<(E + 255) / 256, 256>>>(dst, E);
    scan1_kernel<<<64, 256>>>();
    scan_off_kernel<<<64, 256>>>();
    fill_kernel<<<(E + 255) / 256, 256>>>(src, dst, E);

    // ---- layer 1: relu((agg X) W1 + b1)
    gather128h_kernel<<<n / 8, 256>>>(aggX);
    {
        dim3 grid(H1 / 128, n / 128);
        sgemm_kernel<2, false><<<grid, 256>>>(aggX, W1, bufA, b1, n, F_IN, H1);
    }

    // ---- layer 2: agg(h1 W2) + b2   (xw emitted as fp16)
    {
        dim3 grid(H2 / 128, n / 128);
        sgemm_kernel<0, true><<<grid, 256>>>(bufA, W2, xwh, nullptr, n, H1, H2);
    }
    gather256h_kernel<<<n, 64>>>(b2, bufB);

    // ---- assignment MLP + softmax + group features (fused)
    mlp_kernel<<<n / 16, 256>>>(bufB, fc1b, fc2w, fc2b);

    // ---- 2x2 pooled adjacency
    newadj_kernel<<<256, 256>>>(src, dst, E);

    final_kernel<<<1, 256>>>(out);
}

// round 6
// speedup vs baseline: 9.3031x; 1.0816x over previous
#include <cuda_runtime.h>
#include <cuda_bf16.h>
#include <cuda_fp16.h>
#include <math.h>

#define NN    16384
#define EE    524288
#define F_IN  128
#define H1    256
#define H2    256
#define D1    64

// ---------------- scratch (device globals) ----------------------------------
__device__ int    g_degi[NN];
__device__ int    g_rowstart[NN + 1];
__device__ int    g_cursor[NN];
__device__ int2   g_cedge[EE];          // packed {src, w-as-int}
__device__ float  g_dinv[NN];
__device__ float  g_fc1wT[256 * 64];
__device__ __half g_feath[NN * F_IN];   // fp16 features for gather1
__device__ __half g_xwh [NN * 256];     // fp16 h1*W2 for gather2
__device__ float  g_aggX[NN * F_IN];
__device__ float  g_bufA[NN * 256];     // h1
__device__ float  g_bufB[NN * 256];     // h2
__device__ float  g_assign[NN * 2];
__device__ float  g_group[2 * 256];
__device__ float  g_newadj[4];

__device__ __forceinline__ unsigned f2tf32(float x) {
    unsigned r;
    asm("cvt.rna.tf32.f32 %0, %1;" : "=r"(r) : "f"(x));
    return r;
}

// ---------------- setup: zero + fc1 transpose + feature->half (fused) -------
__global__ void zero_kernel(const float* __restrict__ fc1w, const float* __restrict__ feat) {
    int i = blockIdx.x * blockDim.x + threadIdx.x;   // 0..524287
    if (i < NN)  g_degi[i] = 0;
    if (i < 512) g_group[i] = 0.0f;
    if (i < 4)   g_newadj[i] = 0.0f;
    if (i < 64 * 256) {
        int j = i >> 8, k = i & 255;
        g_fc1wT[k * 64 + j] = fc1w[i];
    }
    float4 v = ((const float4*)feat)[i];
    __half2 h0 = __floats2half2_rn(v.x, v.y);
    __half2 h1 = __floats2half2_rn(v.z, v.w);
    uint2 u;
    u.x = *reinterpret_cast<unsigned int*>(&h0);
    u.y = *reinterpret_cast<unsigned int*>(&h1);
    ((uint2*)g_feath)[i] = u;
}

__global__ void deg_kernel(const int* __restrict__ dst, int E) {
    int e = blockIdx.x * blockDim.x + threadIdx.x;
    if (e < E) atomicAdd(&g_degi[dst[e]], 1);
}

// ---------------- single-launch scan (+dinv): 1 block x 1024, 16 elems/thr --
__global__ void scan_kernel() {
    const int t = threadIdx.x;
    const int lane = t & 31, w = t >> 5;
    const int base = t * 16;
    int loc[16];
    int sum = 0;
#pragma unroll
    for (int j = 0; j < 16; j++) {
        int v = g_degi[base + j];
        g_dinv[base + j] = rsqrtf((float)v + 1.0f);   // +1 self loop
        loc[j] = sum; sum += v;
    }
    int s = sum;
#pragma unroll
    for (int off = 1; off < 32; off <<= 1) {
        int u = __shfl_up_sync(0xffffffffu, s, off);
        if (lane >= off) s += u;
    }
    __shared__ int wsum[32];
    if (lane == 31) wsum[w] = s;
    __syncthreads();
    if (w == 0) {
        int x = wsum[lane];
#pragma unroll
        for (int off = 1; off < 32; off <<= 1) {
            int u = __shfl_up_sync(0xffffffffu, x, off);
            if (lane >= off) x += u;
        }
        wsum[lane] = x;
    }
    __syncthreads();
    int off0 = s - sum + (w > 0 ? wsum[w - 1] : 0);
#pragma unroll
    for (int j = 0; j < 16; j++) {
        int r = off0 + loc[j];
        g_rowstart[base + j] = r;
        g_cursor[base + j] = r;
    }
    if (t == 1023) g_rowstart[NN] = off0 + sum;
}

__global__ void fill_kernel(const int* __restrict__ src, const int* __restrict__ dst, int E) {
    int e = blockIdx.x * blockDim.x + threadIdx.x;
    if (e >= E) return;
    int s = src[e], d = dst[e];
    int p = atomicAdd(&g_cursor[d], 1);
    g_cedge[p] = make_int2(s, __float_as_int(g_dinv[s] * g_dinv[d]));
}

// ---------------- tf32 tensor-core GEMM: 128x128 block, 8 warps -------------
// ACT: 0 = plain, 2 = +bias then relu.  HALF_OUT: store C as __half.
template <int ACT, bool HALF_OUT>
__global__ void __launch_bounds__(256, 2)
tgemm_kernel(const float* __restrict__ A, const float* __restrict__ B,
             void* __restrict__ Cv, const float* __restrict__ bias,
             int M, int K, int Nc) {
    __shared__ unsigned As[2][16][136];   // [k][m], tf32 bits
    __shared__ unsigned Bs[2][16][136];   // [k][n], tf32 bits
    const int tid = threadIdx.x;
    const int rowBase = blockIdx.y * 128;
    const int colBase = blockIdx.x * 128;
    const int wid = tid >> 5, lane = tid & 31;
    const int mBase = (wid >> 1) * 32;    // 4 warps in M
    const int nBase = (wid & 1) * 64;     // 2 warps in N
    const int g = lane >> 2, tg = lane & 3;

    const int ar = tid >> 1;              // 0..127  (A row in tile)
    const int ac = (tid & 1) * 8;         // 0 or 8  (A col in tile)
    const int bk = tid >> 4;              // 0..15   (B row in tile)
    const int bn = (tid & 15) * 8;        // 0..120  (B col in tile)

    const float* Aptr = A + (size_t)(rowBase + ar) * K + ac;
    const float* Bptr = B + (size_t)bk * Nc + colBase + bn;

    float acc[2][8][4];
#pragma unroll
    for (int mt = 0; mt < 2; mt++)
#pragma unroll
        for (int nt = 0; nt < 8; nt++)
#pragma unroll
            for (int q = 0; q < 4; q++) acc[mt][nt][q] = 0.0f;

    float4 a0v = *(const float4*)(Aptr);
    float4 a1v = *(const float4*)(Aptr + 4);
    float4 b0v = *(const float4*)(Bptr);
    float4 b1v = *(const float4*)(Bptr + 4);

    int buf = 0;
    // store stage 0
    {
        As[0][ac + 0][ar] = f2tf32(a0v.x); As[0][ac + 1][ar] = f2tf32(a0v.y);
        As[0][ac + 2][ar] = f2tf32(a0v.z); As[0][ac + 3][ar] = f2tf32(a0v.w);
        As[0][ac + 4][ar] = f2tf32(a1v.x); As[0][ac + 5][ar] = f2tf32(a1v.y);
        As[0][ac + 6][ar] = f2tf32(a1v.z); As[0][ac + 7][ar] = f2tf32(a1v.w);
        unsigned* br = &Bs[0][bk][bn];
        br[0] = f2tf32(b0v.x); br[1] = f2tf32(b0v.y);
        br[2] = f2tf32(b0v.z); br[3] = f2tf32(b0v.w);
        br[4] = f2tf32(b1v.x); br[5] = f2tf32(b1v.y);
        br[6] = f2tf32(b1v.z); br[7] = f2tf32(b1v.w);
    }
    __syncthreads();

    for (int k0 = 16; k0 <= K; k0 += 16) {
        if (k0 < K) {
            a0v = *(const float4*)(Aptr + k0);
            a1v = *(const float4*)(Aptr + k0 + 4);
            b0v = *(const float4*)(Bptr + (size_t)k0 * Nc);
            b1v = *(const float4*)(Bptr + (size_t)k0 * Nc + 4);
        }
#pragma unroll
        for (int kb = 0; kb < 16; kb += 8) {
            unsigned af[2][4];
#pragma unroll
            for (int mt = 0; mt < 2; mt++) {
                int m0 = mBase + mt * 16 + g;
                af[mt][0] = As[buf][kb + tg][m0];
                af[mt][1] = As[buf][kb + tg][m0 + 8];
                af[mt][2] = As[buf][kb + tg + 4][m0];
                af[mt][3] = As[buf][kb + tg + 4][m0 + 8];
            }
#pragma unroll
            for (int nt = 0; nt < 8; nt++) {
                int n0 = nBase + nt * 8 + g;
                unsigned bf0 = Bs[buf][kb + tg][n0];
                unsigned bf1 = Bs[buf][kb + tg + 4][n0];
#pragma unroll
                for (int mt = 0; mt < 2; mt++) {
                    asm volatile(
                        "mma.sync.aligned.m16n8k8.row.col.f32.tf32.tf32.f32 "
                        "{%0,%1,%2,%3}, {%4,%5,%6,%7}, {%8,%9}, {%0,%1,%2,%3};"
                        : "+f"(acc[mt][nt][0]), "+f"(acc[mt][nt][1]),
                          "+f"(acc[mt][nt][2]), "+f"(acc[mt][nt][3])
                        : "r"(af[mt][0]), "r"(af[mt][1]), "r"(af[mt][2]), "r"(af[mt][3]),
                          "r"(bf0), "r"(bf1));
                }
            }
        }
        if (k0 < K) {
            buf ^= 1;
            As[buf][ac + 0][ar] = f2tf32(a0v.x); As[buf][ac + 1][ar] = f2tf32(a0v.y);
            As[buf][ac + 2][ar] = f2tf32(a0v.z); As[buf][ac + 3][ar] = f2tf32(a0v.w);
            As[buf][ac + 4][ar] = f2tf32(a1v.x); As[buf][ac + 5][ar] = f2tf32(a1v.y);
            As[buf][ac + 6][ar] = f2tf32(a1v.z); As[buf][ac + 7][ar] = f2tf32(a1v.w);
            unsigned* br = &Bs[buf][bk][bn];
            br[0] = f2tf32(b0v.x); br[1] = f2tf32(b0v.y);
            br[2] = f2tf32(b0v.z); br[3] = f2tf32(b0v.w);
            br[4] = f2tf32(b1v.x); br[5] = f2tf32(b1v.y);
            br[6] = f2tf32(b1v.z); br[7] = f2tf32(b1v.w);
            __syncthreads();
        }
    }

    // epilogue
#pragma unroll
    for (int mt = 0; mt < 2; mt++) {
        int r0 = rowBase + mBase + mt * 16 + g;
#pragma unroll
        for (int nt = 0; nt < 8; nt++) {
            int c = colBase + nBase + nt * 8 + tg * 2;
            float v0 = acc[mt][nt][0], v1 = acc[mt][nt][1];
            float v2 = acc[mt][nt][2], v3 = acc[mt][nt][3];
            if (ACT > 0) {
                float ba = bias[c], bb = bias[c + 1];
                v0 += ba; v1 += bb; v2 += ba; v3 += bb;
            }
            if (ACT == 2) {
                v0 = fmaxf(v0, 0.0f); v1 = fmaxf(v1, 0.0f);
                v2 = fmaxf(v2, 0.0f); v3 = fmaxf(v3, 0.0f);
            }
            if (HALF_OUT) {
                __half* C = (__half*)Cv;
                __half2 h0 = __floats2half2_rn(v0, v1);
                __half2 h1 = __floats2half2_rn(v2, v3);
                *(__half2*)(C + (size_t)r0 * Nc + c) = h0;
                *(__half2*)(C + (size_t)(r0 + 8) * Nc + c) = h1;
            } else {
                float* C = (float*)Cv;
                *(float2*)(C + (size_t)r0 * Nc + c) = make_float2(v0, v1);
                *(float2*)(C + (size_t)(r0 + 8) * Nc + c) = make_float2(v2, v3);
            }
        }
    }
}

// ---------------- gather aggregation, 128-dim, fp16 source ------------------
__global__ void gather128h_kernel(float* __restrict__ out) {
    const int node = blockIdx.x * 8 + (threadIdx.x >> 5);
    const int t = threadIdx.x & 31;
    const uint2* X = (const uint2*)g_feath;

    const float di = g_dinv[node];
    const float w0 = di * di;
    uint2 u = X[node * 32 + t];
    float2 f0 = __half22float2(*(__half2*)&u.x);
    float2 f1 = __half22float2(*(__half2*)&u.y);
    float4 acc = make_float4(f0.x * w0, f0.y * w0, f1.x * w0, f1.y * w0);

    int k = g_rowstart[node];
    const int end = g_rowstart[node + 1];
    for (; k + 2 <= end; k += 2) {
        int2 e0 = g_cedge[k];
        int2 e1 = g_cedge[k + 1];
        float wa = __int_as_float(e0.y), wb = __int_as_float(e1.y);
        uint2 ua = X[e0.x * 32 + t];
        uint2 ub = X[e1.x * 32 + t];
        float2 a0 = __half22float2(*(__half2*)&ua.x);
        float2 a1 = __half22float2(*(__half2*)&ua.y);
        float2 b0 = __half22float2(*(__half2*)&ub.x);
        float2 b1 = __half22float2(*(__half2*)&ub.y);
        acc.x = fmaf(wa, a0.x, acc.x); acc.y = fmaf(wa, a0.y, acc.y);
        acc.z = fmaf(wa, a1.x, acc.z); acc.w = fmaf(wa, a1.y, acc.w);
        acc.x = fmaf(wb, b0.x, acc.x); acc.y = fmaf(wb, b0.y, acc.y);
        acc.z = fmaf(wb, b1.x, acc.z); acc.w = fmaf(wb, b1.y, acc.w);
    }
    if (k < end) {
        int2 e0 = g_cedge[k];
        float wa = __int_as_float(e0.y);
        uint2 ua = X[e0.x * 32 + t];
        float2 a0 = __half22float2(*(__half2*)&ua.x);
        float2 a1 = __half22float2(*(__half2*)&ua.y);
        acc.x = fmaf(wa, a0.x, acc.x); acc.y = fmaf(wa, a0.y, acc.y);
        acc.z = fmaf(wa, a1.x, acc.z); acc.w = fmaf(wa, a1.y, acc.w);
    }
    ((float4*)out)[node * 32 + t] = acc;
}

// ---------------- gather aggregation, 256-dim, fp16 source, fused bias ------
__global__ void gather256h_kernel(const float* __restrict__ bias, float* __restrict__ out) {
    const int i = blockIdx.x;
    const int t = threadIdx.x;   // 0..63
    const uint2* X = (const uint2*)g_xwh;

    const float di = g_dinv[i];
    const float w0 = di * di;
    uint2 u = X[i * 64 + t];
    float2 f0 = __half22float2(*(__half2*)&u.x);
    float2 f1 = __half22float2(*(__half2*)&u.y);
    float4 acc = make_float4(f0.x * w0, f0.y * w0, f1.x * w0, f1.y * w0);

    int k = g_rowstart[i];
    const int end = g_rowstart[i + 1];
    for (; k + 2 <= end; k += 2) {
        int2 e0 = g_cedge[k];
        int2 e1 = g_cedge[k + 1];
        float wa = __int_as_float(e0.y), wb = __int_as_float(e1.y);
        uint2 ua = X[e0.x * 64 + t];
        uint2 ub = X[e1.x * 64 + t];
        float2 a0 = __half22float2(*(__half2*)&ua.x);
        float2 a1 = __half22float2(*(__half2*)&ua.y);
        float2 b0 = __half22float2(*(__half2*)&ub.x);
        float2 b1 = __half22float2(*(__half2*)&ub.y);
        acc.x = fmaf(wa, a0.x, acc.x); acc.y = fmaf(wa, a0.y, acc.y);
        acc.z = fmaf(wa, a1.x, acc.z); acc.w = fmaf(wa, a1.y, acc.w);
        acc.x = fmaf(wb, b0.x, acc.x); acc.y = fmaf(wb, b0.y, acc.y);
        acc.z = fmaf(wb, b1.x, acc.z); acc.w = fmaf(wb, b1.y, acc.w);
    }
    if (k < end) {
        int2 e0 = g_cedge[k];
        float wa = __int_as_float(e0.y);
        uint2 ua = X[e0.x * 64 + t];
        float2 a0 = __half22float2(*(__half2*)&ua.x);
        float2 a1 = __half22float2(*(__half2*)&ua.y);
        acc.x = fmaf(wa, a0.x, acc.x); acc.y = fmaf(wa, a0.y, acc.y);
        acc.z = fmaf(wa, a1.x, acc.z); acc.w = fmaf(wa, a1.y, acc.w);
    }
    float4 b = ((const float4*)bias)[t];
    acc.x += b.x; acc.y += b.y; acc.z += b.z; acc.w += b.w;
    ((float4*)out)[i * 64 + t] = acc;
}

// ---------------- MLP + softmax + fused group reduction ---------------------
__global__ void mlp_kernel(const float* __restrict__ h2,
                           const float* __restrict__ fc1b,
                           const float* __restrict__ fc2w, const float* __restrict__ fc2b) {
    __shared__ float s_row[16][260];
    __shared__ float s_a1[16][64];
    __shared__ float s_asg[16][2];
    const int t = threadIdx.x;      // 0..255
    const int i0 = blockIdx.x * 16;

#pragma unroll
    for (int l = 0; l < 4; l++) {
        int idx = t + l * 256;
        int row = idx >> 6, c4 = idx & 63;
        float4 v = ((const float4*)(h2 + (size_t)i0 * 256))[idx];
        ((float4*)&s_row[row][0])[c4] = v;
    }
    __syncthreads();

    const int j = t & 63, g = t >> 6;
    float a0 = 0.f, a1 = 0.f, a2 = 0.f, a3 = 0.f;
#pragma unroll 4
    for (int k = 0; k < 256; k++) {
        float wv = g_fc1wT[k * 64 + j];
        a0 = fmaf(s_row[g][k],      wv, a0);
        a1 = fmaf(s_row[g + 4][k],  wv, a1);
        a2 = fmaf(s_row[g + 8][k],  wv, a2);
        a3 = fmaf(s_row[g + 12][k], wv, a3);
    }
    const float bb = fc1b[j];
    s_a1[g][j]      = tanhf(a0 + bb);
    s_a1[g + 4][j]  = tanhf(a1 + bb);
    s_a1[g + 8][j]  = tanhf(a2 + bb);
    s_a1[g + 12][j] = tanhf(a3 + bb);
    __syncthreads();

    if (t < 16) {
        float l0 = fc2b[0], l1 = fc2b[1];
#pragma unroll
        for (int k = 0; k < 64; k++) {
            float av = s_a1[t][k];
            l0 = fmaf(av, fc2w[k],      l0);
            l1 = fmaf(av, fc2w[64 + k], l1);
        }
        float m = fmaxf(l0, l1);
        float e0 = __expf(l0 - m), e1 = __expf(l1 - m);
        float inv = 1.0f / (e0 + e1);
        float p0 = e0 * inv, p1 = e1 * inv;
        s_asg[t][0] = p0; s_asg[t][1] = p1;
        g_assign[(i0 + t) * 2 + 0] = p0;
        g_assign[(i0 + t) * 2 + 1] = p1;
    }
    __syncthreads();

    float p0 = 0.f, p1 = 0.f;
#pragma unroll
    for (int nd = 0; nd < 16; nd++) {
        float v = s_row[nd][t];
        p0 = fmaf(s_asg[nd][0], v, p0);
        p1 = fmaf(s_asg[nd][1], v, p1);
    }
    atomicAdd(&g_group[t], p0);
    atomicAdd(&g_group[256 + t], p1);
}

// ---------------- 2x2 pooled adjacency --------------------------------------
__global__ void newadj_kernel(const int* __restrict__ src, const int* __restrict__ dst, int E) {
    float s00 = 0, s01 = 0, s10 = 0, s11 = 0;
    for (int e = blockIdx.x * blockDim.x + threadIdx.x; e < E; e += gridDim.x * blockDim.x) {
        int s = src[e], d = dst[e];
        float as0 = g_assign[s * 2], as1 = g_assign[s * 2 + 1];
        float ad0 = g_assign[d * 2], ad1 = g_assign[d * 2 + 1];
        s00 = fmaf(as0, ad0, s00);
        s01 = fmaf(as0, ad1, s01);
        s10 = fmaf(as1, ad0, s10);
        s11 = fmaf(as1, ad1, s11);
    }
#pragma unroll
    for (int off = 16; off > 0; off >>= 1) {
        s00 += __shfl_down_sync(0xffffffffu, s00, off);
        s01 += __shfl_down_sync(0xffffffffu, s01, off);
        s10 += __shfl_down_sync(0xffffffffu, s10, off);
        s11 += __shfl_down_sync(0xffffffffu, s11, off);
    }
    __shared__ float sh[4][8];
    int lane = threadIdx.x & 31, w = threadIdx.x >> 5;
    if (lane == 0) { sh[0][w] = s00; sh[1][w] = s01; sh[2][w] = s10; sh[3][w] = s11; }
    __syncthreads();
    if (threadIdx.x < 4) {
        float sum = 0;
        int nw = blockDim.x >> 5;
        for (int k = 0; k < nw; k++) sum += sh[threadIdx.x][k];
        atomicAdd(&g_newadj[threadIdx.x], sum);
    }
}

__global__ void final_kernel(float* __restrict__ out) {
    int t = threadIdx.x;   // 256
    float g0 = g_group[t], g1 = g_group[256 + t];
    out[t]        = 0.5f * (g0 + g1);
    out[256 + t]  = fminf(fmaxf(g0, -100.0f), 100.0f);
    out[512 + t]  = fminf(fmaxf(g1, -100.0f), 100.0f);
    if (t == 0) {
        float n00 = g_newadj[0], n01 = g_newadj[1];
        float n10 = g_newadj[2], n11 = g_newadj[3];
        float d0 = fmaxf(fabsf(n00) + fabsf(n01), 1e-12f);
        float d1 = fmaxf(fabsf(n10) + fabsf(n11), 1e-12f);
        float diag0 = n00 / d0 - 1.0f;
        float diag1 = n11 / d1 - 1.0f;
        out[768] = 0.5f * (diag0 * diag0 + diag1 * diag1);
    }
}

// ---------------- launch ------------------------------------------------------

extern "C" void kernel_launch(void* const* d_in, const int* in_sizes, int n_in,
                              void* d_out, int out_size) {
    const float* features = (const float*)d_in[0];
    const int*   edges    = (const int*)d_in[1];
    const float* W1   = (const float*)d_in[2];
    const float* b1   = (const float*)d_in[3];
    const float* W2   = (const float*)d_in[4];
    const float* b2   = (const float*)d_in[5];
    const float* fc1w = (const float*)d_in[6];
    const float* fc1b = (const float*)d_in[7];
    const float* fc2w = (const float*)d_in[8];
    const float* fc2b = (const float*)d_in[9];
    float* out = (float*)d_out;

    const int n = in_sizes[0] / F_IN;       // 16384
    const int E = in_sizes[1] / 2;          // 524288
    const int* src = edges;
    const int* dst = edges + E;

    float *aggX, *bufA, *bufB;
    __half* xwh;
    cudaGetSymbolAddress((void**)&aggX, g_aggX);
    cudaGetSymbolAddress((void**)&bufA, g_bufA);
    cudaGetSymbolAddress((void**)&bufB, g_bufB);
    cudaGetSymbolAddress((void**)&xwh,  g_xwh);

    // ---- preprocessing
    zero_kernel<<<(n * F_IN / 4 + 255) / 256, 256>>>(fc1w, features);
    deg_kernel<<<(E + 255) / 256, 256>>>(dst, E);
    scan_kernel<<<1, 1024>>>();
    fill_kernel<<<(E + 255) / 256, 256>>>(src, dst, E);

    // ---- layer 1: relu((agg X) W1 + b1)
    gather128h_kernel<<<n / 8, 256>>>(aggX);
    {
        dim3 grid(H1 / 128, n / 128);
        tgemm_kernel<2, false><<<grid, 256>>>(aggX, W1, bufA, b1, n, F_IN, H1);
    }

    // ---- layer 2: agg(h1 W2) + b2  (xw emitted as fp16)
    {
        dim3 grid(H2 / 128, n / 128);
        tgemm_kernel<0, true><<<grid, 256>>>(bufA, W2, xwh, nullptr, n, H1, H2);
    }
    gather256h_kernel<<<n, 64>>>(b2, bufB);

    // ---- assignment MLP + softmax + group features (fused)
    mlp_kernel<<<n / 16, 256>>>(bufB, fc1b, fc2w, fc2b);

    // ---- 2x2 pooled adjacency
    newadj_kernel<<<256, 256>>>(src, dst, E);

    final_kernel<<<1, 256>>>(out);
}

// round 7
// speedup vs baseline: 10.5880x; 1.1381x over previous
#include <cuda_runtime.h>
#include <cuda_bf16.h>
#include <cuda_fp16.h>
#include <math.h>

#define NN    16384
#define EE    524288
#define F_IN  128
#define H1    256
#define H2    256
#define D1    64

// ---------------- scratch (device globals) ----------------------------------
__device__ int    g_degi[NN];
__device__ int    g_rowstart[NN + 1];
__device__ int    g_erank[EE];          // arrival rank of edge within dst list
__device__ int2   g_cedge[EE];          // packed {src, w-as-int}
__device__ float  g_dinv[NN];
__device__ float  g_fc1wT[256 * 64];
__device__ __half g_feath[NN * F_IN];   // fp16 features for gather1
__device__ __half g_xwh [NN * 256];     // fp16 h1*W2 for gather2
__device__ float  g_aggX[NN * F_IN];
__device__ float  g_bufA[NN * 256];     // h1
__device__ float  g_bufB[NN * 256];     // h2
__device__ float  g_assign[NN * 2];
__device__ float  g_group[2 * 256];
__device__ float  g_newadj[4];

__device__ __forceinline__ unsigned f2tf32(float x) {
    unsigned r;
    asm("cvt.rna.tf32.f32 %0, %1;" : "=r"(r) : "f"(x));
    return r;
}

// ---------------- setup: zero + fc1 transpose + feature->half (fused) -------
__global__ void zero_kernel(const float* __restrict__ fc1w, const float* __restrict__ feat) {
    int i = blockIdx.x * blockDim.x + threadIdx.x;   // 0..524287
    if (i < NN)  g_degi[i] = 0;
    if (i < 512) g_group[i] = 0.0f;
    if (i < 4)   g_newadj[i] = 0.0f;
    if (i < 64 * 256) {
        int j = i >> 8, k = i & 255;
        g_fc1wT[k * 64 + j] = fc1w[i];
    }
    float4 v = ((const float4*)feat)[i];
    __half2 h0 = __floats2half2_rn(v.x, v.y);
    __half2 h1 = __floats2half2_rn(v.z, v.w);
    uint2 u;
    u.x = *reinterpret_cast<unsigned int*>(&h0);
    u.y = *reinterpret_cast<unsigned int*>(&h1);
    ((uint2*)g_feath)[i] = u;
}

// degree count + per-edge arrival rank (reuses the same atomic)
__global__ void deg_kernel(const int* __restrict__ dst, int E) {
    int e = blockIdx.x * blockDim.x + threadIdx.x;
    if (e < E) g_erank[e] = atomicAdd(&g_degi[dst[e]], 1);
}

// ---------------- single-launch scan (+dinv): 1 block x 1024, 16 elems/thr --
__global__ void scan_kernel() {
    const int t = threadIdx.x;
    const int lane = t & 31, w = t >> 5;
    const int base = t * 16;
    int loc[16];
    int sum = 0;
#pragma unroll
    for (int j = 0; j < 16; j++) {
        int v = g_degi[base + j];
        g_dinv[base + j] = rsqrtf((float)v + 1.0f);   // +1 self loop
        loc[j] = sum; sum += v;
    }
    int s = sum;
#pragma unroll
    for (int off = 1; off < 32; off <<= 1) {
        int u = __shfl_up_sync(0xffffffffu, s, off);
        if (lane >= off) s += u;
    }
    __shared__ int wsum[32];
    if (lane == 31) wsum[w] = s;
    __syncthreads();
    if (w == 0) {
        int x = wsum[lane];
#pragma unroll
        for (int off = 1; off < 32; off <<= 1) {
            int u = __shfl_up_sync(0xffffffffu, x, off);
            if (lane >= off) x += u;
        }
        wsum[lane] = x;
    }
    __syncthreads();
    int off0 = s - sum + (w > 0 ? wsum[w - 1] : 0);
#pragma unroll
    for (int j = 0; j < 16; j++) {
        g_rowstart[base + j] = off0 + loc[j];
    }
    if (t == 1023) g_rowstart[NN] = off0 + sum;
}

// atomic-free CSR fill using precomputed ranks
__global__ void fill_kernel(const int* __restrict__ src, const int* __restrict__ dst, int E) {
    int e = blockIdx.x * blockDim.x + threadIdx.x;
    if (e >= E) return;
    int s = src[e], d = dst[e];
    int p = g_rowstart[d] + g_erank[e];
    g_cedge[p] = make_int2(s, __float_as_int(g_dinv[s] * g_dinv[d]));
}

// ---------------- tf32 tensor-core GEMM: 128x128 block, 8 warps -------------
template <int ACT, bool HALF_OUT>
__global__ void __launch_bounds__(256, 2)
tgemm_kernel(const float* __restrict__ A, const float* __restrict__ B,
             void* __restrict__ Cv, const float* __restrict__ bias,
             int M, int K, int Nc) {
    __shared__ unsigned As[2][16][136];
    __shared__ unsigned Bs[2][16][136];
    const int tid = threadIdx.x;
    const int rowBase = blockIdx.y * 128;
    const int colBase = blockIdx.x * 128;
    const int wid = tid >> 5, lane = tid & 31;
    const int mBase = (wid >> 1) * 32;
    const int nBase = (wid & 1) * 64;
    const int g = lane >> 2, tg = lane & 3;

    const int ar = tid >> 1;
    const int ac = (tid & 1) * 8;
    const int bk = tid >> 4;
    const int bn = (tid & 15) * 8;

    const float* Aptr = A + (size_t)(rowBase + ar) * K + ac;
    const float* Bptr = B + (size_t)bk * Nc + colBase + bn;

    float acc[2][8][4];
#pragma unroll
    for (int mt = 0; mt < 2; mt++)
#pragma unroll
        for (int nt = 0; nt < 8; nt++)
#pragma unroll
            for (int q = 0; q < 4; q++) acc[mt][nt][q] = 0.0f;

    float4 a0v = *(const float4*)(Aptr);
    float4 a1v = *(const float4*)(Aptr + 4);
    float4 b0v = *(const float4*)(Bptr);
    float4 b1v = *(const float4*)(Bptr + 4);

    int buf = 0;
    {
        As[0][ac + 0][ar] = f2tf32(a0v.x); As[0][ac + 1][ar] = f2tf32(a0v.y);
        As[0][ac + 2][ar] = f2tf32(a0v.z); As[0][ac + 3][ar] = f2tf32(a0v.w);
        As[0][ac + 4][ar] = f2tf32(a1v.x); As[0][ac + 5][ar] = f2tf32(a1v.y);
        As[0][ac + 6][ar] = f2tf32(a1v.z); As[0][ac + 7][ar] = f2tf32(a1v.w);
        unsigned* br = &Bs[0][bk][bn];
        br[0] = f2tf32(b0v.x); br[1] = f2tf32(b0v.y);
        br[2] = f2tf32(b0v.z); br[3] = f2tf32(b0v.w);
        br[4] = f2tf32(b1v.x); br[5] = f2tf32(b1v.y);
        br[6] = f2tf32(b1v.z); br[7] = f2tf32(b1v.w);
    }
    __syncthreads();

    for (int k0 = 16; k0 <= K; k0 += 16) {
        if (k0 < K) {
            a0v = *(const float4*)(Aptr + k0);
            a1v = *(const float4*)(Aptr + k0 + 4);
            b0v = *(const float4*)(Bptr + (size_t)k0 * Nc);
            b1v = *(const float4*)(Bptr + (size_t)k0 * Nc + 4);
        }
#pragma unroll
        for (int kb = 0; kb < 16; kb += 8) {
            unsigned af[2][4];
#pragma unroll
            for (int mt = 0; mt < 2; mt++) {
                int m0 = mBase + mt * 16 + g;
                af[mt][0] = As[buf][kb + tg][m0];
                af[mt][1] = As[buf][kb + tg][m0 + 8];
                af[mt][2] = As[buf][kb + tg + 4][m0];
                af[mt][3] = As[buf][kb + tg + 4][m0 + 8];
            }
#pragma unroll
            for (int nt = 0; nt < 8; nt++) {
                int n0 = nBase + nt * 8 + g;
                unsigned bf0 = Bs[buf][kb + tg][n0];
                unsigned bf1 = Bs[buf][kb + tg + 4][n0];
#pragma unroll
                for (int mt = 0; mt < 2; mt++) {
                    asm volatile(
                        "mma.sync.aligned.m16n8k8.row.col.f32.tf32.tf32.f32 "
                        "{%0,%1,%2,%3}, {%4,%5,%6,%7}, {%8,%9}, {%0,%1,%2,%3};"
                        : "+f"(acc[mt][nt][0]), "+f"(acc[mt][nt][1]),
                          "+f"(acc[mt][nt][2]), "+f"(acc[mt][nt][3])
                        : "r"(af[mt][0]), "r"(af[mt][1]), "r"(af[mt][2]), "r"(af[mt][3]),
                          "r"(bf0), "r"(bf1));
                }
            }
        }
        if (k0 < K) {
            buf ^= 1;
            As[buf][ac + 0][ar] = f2tf32(a0v.x); As[buf][ac + 1][ar] = f2tf32(a0v.y);
            As[buf][ac + 2][ar] = f2tf32(a0v.z); As[buf][ac + 3][ar] = f2tf32(a0v.w);
            As[buf][ac + 4][ar] = f2tf32(a1v.x); As[buf][ac + 5][ar] = f2tf32(a1v.y);
            As[buf][ac + 6][ar] = f2tf32(a1v.z); As[buf][ac + 7][ar] = f2tf32(a1v.w);
            unsigned* br = &Bs[buf][bk][bn];
            br[0] = f2tf32(b0v.x); br[1] = f2tf32(b0v.y);
            br[2] = f2tf32(b0v.z); br[3] = f2tf32(b0v.w);
            br[4] = f2tf32(b1v.x); br[5] = f2tf32(b1v.y);
            br[6] = f2tf32(b1v.z); br[7] = f2tf32(b1v.w);
            __syncthreads();
        }
    }

#pragma unroll
    for (int mt = 0; mt < 2; mt++) {
        int r0 = rowBase + mBase + mt * 16 + g;
#pragma unroll
        for (int nt = 0; nt < 8; nt++) {
            int c = colBase + nBase + nt * 8 + tg * 2;
            float v0 = acc[mt][nt][0], v1 = acc[mt][nt][1];
            float v2 = acc[mt][nt][2], v3 = acc[mt][nt][3];
            if (ACT > 0) {
                float ba = bias[c], bb = bias[c + 1];
                v0 += ba; v1 += bb; v2 += ba; v3 += bb;
            }
            if (ACT == 2) {
                v0 = fmaxf(v0, 0.0f); v1 = fmaxf(v1, 0.0f);
                v2 = fmaxf(v2, 0.0f); v3 = fmaxf(v3, 0.0f);
            }
            if (HALF_OUT) {
                __half* C = (__half*)Cv;
                *(__half2*)(C + (size_t)r0 * Nc + c) = __floats2half2_rn(v0, v1);
                *(__half2*)(C + (size_t)(r0 + 8) * Nc + c) = __floats2half2_rn(v2, v3);
            } else {
                float* C = (float*)Cv;
                *(float2*)(C + (size_t)r0 * Nc + c) = make_float2(v0, v1);
                *(float2*)(C + (size_t)(r0 + 8) * Nc + c) = make_float2(v2, v3);
            }
        }
    }
}

// ---------------- gather helpers ---------------------------------------------
__device__ __forceinline__ void fma_h4(float4& acc, float w, uint2 u) {
    float2 a0 = __half22float2(*(__half2*)&u.x);
    float2 a1 = __half22float2(*(__half2*)&u.y);
    acc.x = fmaf(w, a0.x, acc.x); acc.y = fmaf(w, a0.y, acc.y);
    acc.z = fmaf(w, a1.x, acc.z); acc.w = fmaf(w, a1.y, acc.w);
}

// ---------------- gather aggregation, 128-dim, fp16 source ------------------
__global__ void gather128h_kernel(float* __restrict__ out) {
    const int node = blockIdx.x * 8 + (threadIdx.x >> 5);
    const int t = threadIdx.x & 31;
    const uint2* X = (const uint2*)g_feath;

    const float di = g_dinv[node];
    const float w0 = di * di;
    uint2 u = X[node * 32 + t];
    float2 f0 = __half22float2(*(__half2*)&u.x);
    float2 f1 = __half22float2(*(__half2*)&u.y);
    float4 acc = make_float4(f0.x * w0, f0.y * w0, f1.x * w0, f1.y * w0);

    int k = g_rowstart[node];
    const int end = g_rowstart[node + 1];
    for (; k + 4 <= end; k += 4) {
        int2 e0 = g_cedge[k];
        int2 e1 = g_cedge[k + 1];
        int2 e2 = g_cedge[k + 2];
        int2 e3 = g_cedge[k + 3];
        uint2 u0 = X[e0.x * 32 + t];
        uint2 u1 = X[e1.x * 32 + t];
        uint2 u2 = X[e2.x * 32 + t];
        uint2 u3 = X[e3.x * 32 + t];
        fma_h4(acc, __int_as_float(e0.y), u0);
        fma_h4(acc, __int_as_float(e1.y), u1);
        fma_h4(acc, __int_as_float(e2.y), u2);
        fma_h4(acc, __int_as_float(e3.y), u3);
    }
    for (; k < end; k++) {
        int2 e0 = g_cedge[k];
        fma_h4(acc, __int_as_float(e0.y), X[e0.x * 32 + t]);
    }
    ((float4*)out)[node * 32 + t] = acc;
}

// ---------------- gather aggregation, 256-dim, fp16 source, fused bias ------
__global__ void gather256h_kernel(const float* __restrict__ bias, float* __restrict__ out) {
    const int i = blockIdx.x;
    const int t = threadIdx.x;   // 0..63
    const uint2* X = (const uint2*)g_xwh;

    const float di = g_dinv[i];
    const float w0 = di * di;
    uint2 u = X[i * 64 + t];
    float2 f0 = __half22float2(*(__half2*)&u.x);
    float2 f1 = __half22float2(*(__half2*)&u.y);
    float4 acc = make_float4(f0.x * w0, f0.y * w0, f1.x * w0, f1.y * w0);

    int k = g_rowstart[i];
    const int end = g_rowstart[i + 1];
    for (; k + 4 <= end; k += 4) {
        int2 e0 = g_cedge[k];
        int2 e1 = g_cedge[k + 1];
        int2 e2 = g_cedge[k + 2];
        int2 e3 = g_cedge[k + 3];
        uint2 u0 = X[e0.x * 64 + t];
        uint2 u1 = X[e1.x * 64 + t];
        uint2 u2 = X[e2.x * 64 + t];
        uint2 u3 = X[e3.x * 64 + t];
        fma_h4(acc, __int_as_float(e0.y), u0);
        fma_h4(acc, __int_as_float(e1.y), u1);
        fma_h4(acc, __int_as_float(e2.y), u2);
        fma_h4(acc, __int_as_float(e3.y), u3);
    }
    for (; k < end; k++) {
        int2 e0 = g_cedge[k];
        fma_h4(acc, __int_as_float(e0.y), X[e0.x * 64 + t]);
    }
    float4 b = ((const float4*)bias)[t];
    acc.x += b.x; acc.y += b.y; acc.z += b.z; acc.w += b.w;
    ((float4*)out)[i * 64 + t] = acc;
}

// ---------------- MLP + softmax + fused group reduction ---------------------
// 32 nodes per block, 256 threads
__global__ void mlp_kernel(const float* __restrict__ h2,
                           const float* __restrict__ fc1b,
                           const float* __restrict__ fc2w, const float* __restrict__ fc2b) {
    __shared__ float s_row[32][260];
    __shared__ float s_a1[32][64];
    __shared__ float s_asg[32][2];
    const int t = threadIdx.x;      // 0..255
    const int i0 = blockIdx.x * 32;

#pragma unroll
    for (int l = 0; l < 8; l++) {
        int idx = t + l * 256;              // 0..2047 float4 over 32 rows
        int row = idx >> 6, c4 = idx & 63;
        float4 v = ((const float4*)(h2 + (size_t)i0 * 256))[idx];
        ((float4*)&s_row[row][0])[c4] = v;
    }
    __syncthreads();

    const int j = t & 63, g = t >> 6;   // thread handles nodes g, g+4, ..., g+28
    float a[8];
#pragma unroll
    for (int m = 0; m < 8; m++) a[m] = 0.0f;
#pragma unroll 4
    for (int k = 0; k < 256; k++) {
        float wv = g_fc1wT[k * 64 + j];
#pragma unroll
        for (int m = 0; m < 8; m++)
            a[m] = fmaf(s_row[g + 4 * m][k], wv, a[m]);
    }
    const float bb = fc1b[j];
#pragma unroll
    for (int m = 0; m < 8; m++)
        s_a1[g + 4 * m][j] = tanhf(a[m] + bb);
    __syncthreads();

    if (t < 32) {
        float l0 = fc2b[0], l1 = fc2b[1];
#pragma unroll
        for (int k = 0; k < 64; k++) {
            float av = s_a1[t][k];
            l0 = fmaf(av, fc2w[k],      l0);
            l1 = fmaf(av, fc2w[64 + k], l1);
        }
        float m = fmaxf(l0, l1);
        float e0 = __expf(l0 - m), e1 = __expf(l1 - m);
        float inv = 1.0f / (e0 + e1);
        float p0 = e0 * inv, p1 = e1 * inv;
        s_asg[t][0] = p0; s_asg[t][1] = p1;
        g_assign[(i0 + t) * 2 + 0] = p0;
        g_assign[(i0 + t) * 2 + 1] = p1;
    }
    __syncthreads();

    // fused group partial: feature f = t (0..255)
    float p0 = 0.f, p1 = 0.f;
#pragma unroll
    for (int nd = 0; nd < 32; nd++) {
        float v = s_row[nd][t];
        p0 = fmaf(s_asg[nd][0], v, p0);
        p1 = fmaf(s_asg[nd][1], v, p1);
    }
    atomicAdd(&g_group[t], p0);
    atomicAdd(&g_group[256 + t], p1);
}

// ---------------- 2x2 pooled adjacency --------------------------------------
__global__ void newadj_kernel(const int* __restrict__ src, const int* __restrict__ dst, int E) {
    float s00 = 0, s01 = 0, s10 = 0, s11 = 0;
    for (int e = blockIdx.x * blockDim.x + threadIdx.x; e < E; e += gridDim.x * blockDim.x) {
        int s = src[e], d = dst[e];
        float as0 = g_assign[s * 2], as1 = g_assign[s * 2 + 1];
        float ad0 = g_assign[d * 2], ad1 = g_assign[d * 2 + 1];
        s00 = fmaf(as0, ad0, s00);
        s01 = fmaf(as0, ad1, s01);
        s10 = fmaf(as1, ad0, s10);
        s11 = fmaf(as1, ad1, s11);
    }
#pragma unroll
    for (int off = 16; off > 0; off >>= 1) {
        s00 += __shfl_down_sync(0xffffffffu, s00, off);
        s01 += __shfl_down_sync(0xffffffffu, s01, off);
        s10 += __shfl_down_sync(0xffffffffu, s10, off);
        s11 += __shfl_down_sync(0xffffffffu, s11, off);
    }
    __shared__ float sh[4][8];
    int lane = threadIdx.x & 31, w = threadIdx.x >> 5;
    if (lane == 0) { sh[0][w] = s00; sh[1][w] = s01; sh[2][w] = s10; sh[3][w] = s11; }
    __syncthreads();
    if (threadIdx.x < 4) {
        float sum = 0;
        int nw = blockDim.x >> 5;
        for (int k = 0; k < nw; k++) sum += sh[threadIdx.x][k];
        atomicAdd(&g_newadj[threadIdx.x], sum);
    }
}

__global__ void final_kernel(float* __restrict__ out) {
    int t = threadIdx.x;   // 256
    float g0 = g_group[t], g1 = g_group[256 + t];
    out[t]        = 0.5f * (g0 + g1);
    out[256 + t]  = fminf(fmaxf(g0, -100.0f), 100.0f);
    out[512 + t]  = fminf(fmaxf(g1, -100.0f), 100.0f);
    if (t == 0) {
        float n00 = g_newadj[0], n01 = g_newadj[1];
        float n10 = g_newadj[2], n11 = g_newadj[3];
        float d0 = fmaxf(fabsf(n00) + fabsf(n01), 1e-12f);
        float d1 = fmaxf(fabsf(n10) + fabsf(n11), 1e-12f);
        float diag0 = n00 / d0 - 1.0f;
        float diag1 = n11 / d1 - 1.0f;
        out[768] = 0.5f * (diag0 * diag0 + diag1 * diag1);
    }
}

// ---------------- launch ------------------------------------------------------

extern "C" void kernel_launch(void* const* d_in, const int* in_sizes, int n_in,
                              void* d_out, int out_size) {
    const float* features = (const float*)d_in[0];
    const int*   edges    = (const int*)d_in[1];
    const float* W1   = (const float*)d_in[2];
    const float* b1   = (const float*)d_in[3];
    const float* W2   = (const float*)d_in[4];
    const float* b2   = (const float*)d_in[5];
    const float* fc1w = (const float*)d_in[6];
    const float* fc1b = (const float*)d_in[7];
    const float* fc2w = (const float*)d_in[8];
    const float* fc2b = (const float*)d_in[9];
    float* out = (float*)d_out;

    const int n = in_sizes[0] / F_IN;       // 16384
    const int E = in_sizes[1] / 2;          // 524288
    const int* src = edges;
    const int* dst = edges + E;

    float *aggX, *bufA, *bufB;
    __half* xwh;
    cudaGetSymbolAddress((void**)&aggX, g_aggX);
    cudaGetSymbolAddress((void**)&bufA, g_bufA);
    cudaGetSymbolAddress((void**)&bufB, g_bufB);
    cudaGetSymbolAddress((void**)&xwh,  g_xwh);

    // ---- preprocessing
    zero_kernel<<<(n * F_IN / 4 + 255) / 256, 256>>>(fc1w, features);
    deg_kernel<<<(E + 255) / 256, 256>>>(dst, E);
    scan_kernel<<<1, 1024>>>();
    fill_kernel<<<(E + 255) / 256, 256>>>(src, dst, E);

    // ---- layer 1: relu((agg X) W1 + b1)
    gather128h_kernel<<<n / 8, 256>>>(aggX);
    {
        dim3 grid(H1 / 128, n / 128);
        tgemm_kernel<2, false><<<grid, 256>>>(aggX, W1, bufA, b1, n, F_IN, H1);
    }

    // ---- layer 2: agg(h1 W2) + b2  (xw emitted as fp16)
    {
        dim3 grid(H2 / 128, n / 128);
        tgemm_kernel<0, true><<<grid, 256>>>(bufA, W2, xwh, nullptr, n, H1, H2);
    }
    gather256h_kernel<<<n, 64>>>(b2, bufB);

    // ---- assignment MLP + softmax + group features (fused)
    mlp_kernel<<<n / 32, 256>>>(bufB, fc1b, fc2w, fc2b);

    // ---- 2x2 pooled adjacency
    newadj_kernel<<<256, 256>>>(src, dst, E);

    final_kernel<<<1, 256>>>(out);
}

// round 8
// speedup vs baseline: 11.1939x; 1.0572x over previous
#include <cuda_runtime.h>
#include <cuda_bf16.h>
#include <cuda_fp16.h>
#include <math.h>

#define NN    16384
#define EE    524288
#define F_IN  128
#define H1    256
#define H2    256
#define D1    64

// ---------------- scratch (device globals) ----------------------------------
__device__ int    g_degi[NN];
__device__ int    g_rowstart[NN + 1];
__device__ int    g_erank[EE];
__device__ int2   g_cedge[EE];
__device__ float  g_dinv[NN];
__device__ float  g_fc1wT[256 * 64];
__device__ __half g_w1h[256 * 128];     // W1^T as half [n][k]
__device__ __half g_w2h[256 * 256];     // W2^T as half [n][k]
__device__ __half g_feath[NN * F_IN];   // fp16 features
__device__ __half g_aggXh[NN * F_IN];   // fp16 aggregated features
__device__ __half g_bufAh[NN * 256];    // fp16 h1
__device__ __half g_xwh [NN * 256];     // fp16 h1*W2
__device__ float  g_bufB[NN * 256];     // h2 (fp32)
__device__ float  g_assign[NN * 2];
__device__ float  g_group[2 * 256];
__device__ float  g_newadj[4];
__device__ int    g_done;

// ---------------- setup: zero + transposes + feature->half (fused) ----------
__global__ void zero_kernel(const float* __restrict__ fc1w,
                            const float* __restrict__ W1, const float* __restrict__ W2,
                            const float* __restrict__ feat) {
    int i = blockIdx.x * blockDim.x + threadIdx.x;   // 0..524287
    if (i < NN)  g_degi[i] = 0;
    if (i < 512) g_group[i] = 0.0f;
    if (i < 4)   g_newadj[i] = 0.0f;
    if (i == 0)  g_done = 0;
    if (i < 64 * 256) {                 // fc1w [64][256] -> fc1wT [256][64]
        int j = i >> 8, k = i & 255;
        g_fc1wT[k * 64 + j] = fc1w[i];
    }
    if (i < 256 * 128) {                // W1 [128][256] -> w1h [n=256][k=128]
        int nw = i >> 7, k = i & 127;
        g_w1h[i] = __float2half_rn(W1[k * 256 + nw]);
    }
    if (i < 256 * 256) {                // W2 [256][256] -> w2h [n][k]
        int nw = i >> 8, k = i & 255;
        g_w2h[i] = __float2half_rn(W2[k * 256 + nw]);
    }
    float4 v = ((const float4*)feat)[i];
    __half2 h0 = __floats2half2_rn(v.x, v.y);
    __half2 h1 = __floats2half2_rn(v.z, v.w);
    uint2 u;
    u.x = *reinterpret_cast<unsigned int*>(&h0);
    u.y = *reinterpret_cast<unsigned int*>(&h1);
    ((uint2*)g_feath)[i] = u;
}

// degree count + per-edge arrival rank
__global__ void deg_kernel(const int* __restrict__ dst, int E) {
    int e = blockIdx.x * blockDim.x + threadIdx.x;
    if (e < E) g_erank[e] = atomicAdd(&g_degi[dst[e]], 1);
}

// ---------------- single-launch scan (+dinv): 1 block x 1024 ----------------
__global__ void scan_kernel() {
    const int t = threadIdx.x;
    const int lane = t & 31, w = t >> 5;
    const int base = t * 16;
    int loc[16];
    int sum = 0;
#pragma unroll
    for (int j = 0; j < 16; j++) {
        int v = g_degi[base + j];
        g_dinv[base + j] = rsqrtf((float)v + 1.0f);
        loc[j] = sum; sum += v;
    }
    int s = sum;
#pragma unroll
    for (int off = 1; off < 32; off <<= 1) {
        int u = __shfl_up_sync(0xffffffffu, s, off);
        if (lane >= off) s += u;
    }
    __shared__ int wsum[32];
    if (lane == 31) wsum[w] = s;
    __syncthreads();
    if (w == 0) {
        int x = wsum[lane];
#pragma unroll
        for (int off = 1; off < 32; off <<= 1) {
            int u = __shfl_up_sync(0xffffffffu, x, off);
            if (lane >= off) x += u;
        }
        wsum[lane] = x;
    }
    __syncthreads();
    int off0 = s - sum + (w > 0 ? wsum[w - 1] : 0);
#pragma unroll
    for (int j = 0; j < 16; j++) g_rowstart[base + j] = off0 + loc[j];
    if (t == 1023) g_rowstart[NN] = off0 + sum;
}

// atomic-free CSR fill, 2 edges/thread
__global__ void fill_kernel(const int* __restrict__ src, const int* __restrict__ dst, int E) {
    int e = (blockIdx.x * blockDim.x + threadIdx.x) * 2;
    if (e + 1 < E) {
        int s0 = src[e], d0 = dst[e], r0 = g_erank[e];
        int s1 = src[e + 1], d1 = dst[e + 1], r1 = g_erank[e + 1];
        float ds0 = g_dinv[s0], dd0 = g_dinv[d0];
        float ds1 = g_dinv[s1], dd1 = g_dinv[d1];
        int p0 = g_rowstart[d0] + r0;
        int p1 = g_rowstart[d1] + r1;
        g_cedge[p0] = make_int2(s0, __float_as_int(ds0 * dd0));
        g_cedge[p1] = make_int2(s1, __float_as_int(ds1 * dd1));
    } else if (e < E) {
        int s0 = src[e], d0 = dst[e];
        int p0 = g_rowstart[d0] + g_erank[e];
        g_cedge[p0] = make_int2(s0, __float_as_int(g_dinv[s0] * g_dinv[d0]));
    }
}

// ---------------- fp16 tensor-core GEMM (m16n8k16) ---------------------------
// A: [M][K] half row-major. B: [Nc][K] half (pre-transposed). C per HALF_OUT.
// ACT: 0 = plain, 2 = +bias then relu.
template <int ACT, bool HALF_OUT>
__global__ void __launch_bounds__(256, 2)
hgemm_kernel(const __half* __restrict__ A, const __half* __restrict__ B,
             void* __restrict__ Cv, const float* __restrict__ bias,
             int M, int K, int Nc) {
    __shared__ __half As[2][128][16];
    __shared__ __half Bs[2][128][16];
    const int tid = threadIdx.x;
    const int rowBase = blockIdx.y * 128;
    const int colBase = blockIdx.x * 128;
    const int wid = tid >> 5, lane = tid & 31;
    const int mBase = (wid >> 1) * 32;
    const int nBase = (wid & 1) * 64;
    const int g = lane >> 2, tg = lane & 3;

    const int ar = tid >> 1;             // 0..127
    const int ac = (tid & 1) * 8;        // 0 or 8

    const __half* Aptr = A + (size_t)(rowBase + ar) * K + ac;
    const __half* Bptr = B + (size_t)(colBase + ar) * K + ac;

    float acc[2][8][4];
#pragma unroll
    for (int mt = 0; mt < 2; mt++)
#pragma unroll
        for (int nt = 0; nt < 8; nt++)
#pragma unroll
            for (int q = 0; q < 4; q++) acc[mt][nt][q] = 0.0f;

    uint4 av = *(const uint4*)Aptr;
    uint4 bv = *(const uint4*)Bptr;
    int buf = 0;
    *(uint4*)&As[0][ar][ac] = av;
    *(uint4*)&Bs[0][ar][ac] = bv;
    __syncthreads();

    for (int k0 = 16; k0 <= K; k0 += 16) {
        if (k0 < K) {
            av = *(const uint4*)(Aptr + k0);
            bv = *(const uint4*)(Bptr + k0);
        }
        unsigned af[2][4];
#pragma unroll
        for (int mt = 0; mt < 2; mt++) {
            int m0 = mBase + mt * 16 + g;
            af[mt][0] = *(const unsigned*)&As[buf][m0][2 * tg];
            af[mt][1] = *(const unsigned*)&As[buf][m0 + 8][2 * tg];
            af[mt][2] = *(const unsigned*)&As[buf][m0][2 * tg + 8];
            af[mt][3] = *(const unsigned*)&As[buf][m0 + 8][2 * tg + 8];
        }
#pragma unroll
        for (int nt = 0; nt < 8; nt++) {
            int n0 = nBase + nt * 8 + g;
            unsigned bf0 = *(const unsigned*)&Bs[buf][n0][2 * tg];
            unsigned bf1 = *(const unsigned*)&Bs[buf][n0][2 * tg + 8];
#pragma unroll
            for (int mt = 0; mt < 2; mt++) {
                asm volatile(
                    "mma.sync.aligned.m16n8k16.row.col.f32.f16.f16.f32 "
                    "{%0,%1,%2,%3}, {%4,%5,%6,%7}, {%8,%9}, {%0,%1,%2,%3};"
                    : "+f"(acc[mt][nt][0]), "+f"(acc[mt][nt][1]),
                      "+f"(acc[mt][nt][2]), "+f"(acc[mt][nt][3])
                    : "r"(af[mt][0]), "r"(af[mt][1]), "r"(af[mt][2]), "r"(af[mt][3]),
                      "r"(bf0), "r"(bf1));
            }
        }
        if (k0 < K) {
            buf ^= 1;
            *(uint4*)&As[buf][ar][ac] = av;
            *(uint4*)&Bs[buf][ar][ac] = bv;
            __syncthreads();
        }
    }

#pragma unroll
    for (int mt = 0; mt < 2; mt++) {
        int r0 = rowBase + mBase + mt * 16 + g;
#pragma unroll
        for (int nt = 0; nt < 8; nt++) {
            int c = colBase + nBase + nt * 8 + tg * 2;
            float v0 = acc[mt][nt][0], v1 = acc[mt][nt][1];
            float v2 = acc[mt][nt][2], v3 = acc[mt][nt][3];
            if (ACT > 0) {
                float ba = bias[c], bb = bias[c + 1];
                v0 += ba; v1 += bb; v2 += ba; v3 += bb;
            }
            if (ACT == 2) {
                v0 = fmaxf(v0, 0.0f); v1 = fmaxf(v1, 0.0f);
                v2 = fmaxf(v2, 0.0f); v3 = fmaxf(v3, 0.0f);
            }
            if (HALF_OUT) {
                __half* C = (__half*)Cv;
                *(__half2*)(C + (size_t)r0 * Nc + c) = __floats2half2_rn(v0, v1);
                *(__half2*)(C + (size_t)(r0 + 8) * Nc + c) = __floats2half2_rn(v2, v3);
            } else {
                float* C = (float*)Cv;
                *(float2*)(C + (size_t)r0 * Nc + c) = make_float2(v0, v1);
                *(float2*)(C + (size_t)(r0 + 8) * Nc + c) = make_float2(v2, v3);
            }
        }
    }
}

// ---------------- gather helpers ---------------------------------------------
__device__ __forceinline__ void fma_h4(float4& acc, float w, uint2 u) {
    float2 a0 = __half22float2(*(__half2*)&u.x);
    float2 a1 = __half22float2(*(__half2*)&u.y);
    acc.x = fmaf(w, a0.x, acc.x); acc.y = fmaf(w, a0.y, acc.y);
    acc.z = fmaf(w, a1.x, acc.z); acc.w = fmaf(w, a1.y, acc.w);
}

// ---------------- gather aggregation, 128-dim, fp16 in/out ------------------
__global__ void gather128h_kernel() {
    const int node = blockIdx.x * 8 + (threadIdx.x >> 5);
    const int t = threadIdx.x & 31;
    const uint2* X = (const uint2*)g_feath;

    const float di = g_dinv[node];
    const float w0 = di * di;
    uint2 u = X[node * 32 + t];
    float2 f0 = __half22float2(*(__half2*)&u.x);
    float2 f1 = __half22float2(*(__half2*)&u.y);
    float4 acc = make_float4(f0.x * w0, f0.y * w0, f1.x * w0, f1.y * w0);

    int k = g_rowstart[node];
    const int end = g_rowstart[node + 1];
    for (; k + 4 <= end; k += 4) {
        int2 e0 = g_cedge[k];
        int2 e1 = g_cedge[k + 1];
        int2 e2 = g_cedge[k + 2];
        int2 e3 = g_cedge[k + 3];
        uint2 u0 = X[e0.x * 32 + t];
        uint2 u1 = X[e1.x * 32 + t];
        uint2 u2 = X[e2.x * 32 + t];
        uint2 u3 = X[e3.x * 32 + t];
        fma_h4(acc, __int_as_float(e0.y), u0);
        fma_h4(acc, __int_as_float(e1.y), u1);
        fma_h4(acc, __int_as_float(e2.y), u2);
        fma_h4(acc, __int_as_float(e3.y), u3);
    }
    for (; k < end; k++) {
        int2 e0 = g_cedge[k];
        fma_h4(acc, __int_as_float(e0.y), X[e0.x * 32 + t]);
    }
    __half2 h0 = __floats2half2_rn(acc.x, acc.y);
    __half2 h1 = __floats2half2_rn(acc.z, acc.w);
    uint2 o;
    o.x = *reinterpret_cast<unsigned int*>(&h0);
    o.y = *reinterpret_cast<unsigned int*>(&h1);
    ((uint2*)g_aggXh)[node * 32 + t] = o;
}

// ---------------- gather aggregation, 256-dim, fp16 source, fused bias ------
__global__ void gather256h_kernel(const float* __restrict__ bias, float* __restrict__ out) {
    const int i = blockIdx.x;
    const int t = threadIdx.x;   // 0..63
    const uint2* X = (const uint2*)g_xwh;

    const float di = g_dinv[i];
    const float w0 = di * di;
    uint2 u = X[i * 64 + t];
    float2 f0 = __half22float2(*(__half2*)&u.x);
    float2 f1 = __half22float2(*(__half2*)&u.y);
    float4 acc = make_float4(f0.x * w0, f0.y * w0, f1.x * w0, f1.y * w0);

    int k = g_rowstart[i];
    const int end = g_rowstart[i + 1];
    for (; k + 4 <= end; k += 4) {
        int2 e0 = g_cedge[k];
        int2 e1 = g_cedge[k + 1];
        int2 e2 = g_cedge[k + 2];
        int2 e3 = g_cedge[k + 3];
        uint2 u0 = X[e0.x * 64 + t];
        uint2 u1 = X[e1.x * 64 + t];
        uint2 u2 = X[e2.x * 64 + t];
        uint2 u3 = X[e3.x * 64 + t];
        fma_h4(acc, __int_as_float(e0.y), u0);
        fma_h4(acc, __int_as_float(e1.y), u1);
        fma_h4(acc, __int_as_float(e2.y), u2);
        fma_h4(acc, __int_as_float(e3.y), u3);
    }
    for (; k < end; k++) {
        int2 e0 = g_cedge[k];
        fma_h4(acc, __int_as_float(e0.y), X[e0.x * 64 + t]);
    }
    float4 b = ((const float4*)bias)[t];
    acc.x += b.x; acc.y += b.y; acc.z += b.z; acc.w += b.w;
    ((float4*)out)[i * 64 + t] = acc;
}

// ---------------- MLP + softmax + fused group reduction ---------------------
__global__ void mlp_kernel(const float* __restrict__ h2,
                           const float* __restrict__ fc1b,
                           const float* __restrict__ fc2w, const float* __restrict__ fc2b) {
    __shared__ float s_row[32][260];
    __shared__ float s_a1[32][64];
    __shared__ float s_asg[32][2];
    const int t = threadIdx.x;      // 0..255
    const int i0 = blockIdx.x * 32;

#pragma unroll
    for (int l = 0; l < 8; l++) {
        int idx = t + l * 256;
        int row = idx >> 6, c4 = idx & 63;
        float4 v = ((const float4*)(h2 + (size_t)i0 * 256))[idx];
        ((float4*)&s_row[row][0])[c4] = v;
    }
    __syncthreads();

    const int j = t & 63, g = t >> 6;
    float a[8];
#pragma unroll
    for (int m = 0; m < 8; m++) a[m] = 0.0f;
#pragma unroll 4
    for (int k = 0; k < 256; k++) {
        float wv = g_fc1wT[k * 64 + j];
#pragma unroll
        for (int m = 0; m < 8; m++)
            a[m] = fmaf(s_row[g + 4 * m][k], wv, a[m]);
    }
    const float bb = fc1b[j];
#pragma unroll
    for (int m = 0; m < 8; m++)
        s_a1[g + 4 * m][j] = tanhf(a[m] + bb);
    __syncthreads();

    if (t < 32) {
        float l0 = fc2b[0], l1 = fc2b[1];
#pragma unroll
        for (int k = 0; k < 64; k++) {
            float av = s_a1[t][k];
            l0 = fmaf(av, fc2w[k],      l0);
            l1 = fmaf(av, fc2w[64 + k], l1);
        }
        float m = fmaxf(l0, l1);
        float e0 = __expf(l0 - m), e1 = __expf(l1 - m);
        float inv = 1.0f / (e0 + e1);
        float p0 = e0 * inv, p1 = e1 * inv;
        s_asg[t][0] = p0; s_asg[t][1] = p1;
        g_assign[(i0 + t) * 2 + 0] = p0;
        g_assign[(i0 + t) * 2 + 1] = p1;
    }
    __syncthreads();

    float p0 = 0.f, p1 = 0.f;
#pragma unroll
    for (int nd = 0; nd < 32; nd++) {
        float v = s_row[nd][t];
        p0 = fmaf(s_asg[nd][0], v, p0);
        p1 = fmaf(s_asg[nd][1], v, p1);
    }
    atomicAdd(&g_group[t], p0);
    atomicAdd(&g_group[256 + t], p1);
}

// ---------------- 2x2 pooled adjacency + fused final output -----------------
__global__ void newadj_kernel(const int* __restrict__ src, const int* __restrict__ dst,
                              int E, float* __restrict__ out) {
    float s00 = 0, s01 = 0, s10 = 0, s11 = 0;
    for (int e = blockIdx.x * blockDim.x + threadIdx.x; e < E; e += gridDim.x * blockDim.x) {
        int s = src[e], d = dst[e];
        float as0 = g_assign[s * 2], as1 = g_assign[s * 2 + 1];
        float ad0 = g_assign[d * 2], ad1 = g_assign[d * 2 + 1];
        s00 = fmaf(as0, ad0, s00);
        s01 = fmaf(as0, ad1, s01);
        s10 = fmaf(as1, ad0, s10);
        s11 = fmaf(as1, ad1, s11);
    }
#pragma unroll
    for (int off = 16; off > 0; off >>= 1) {
        s00 += __shfl_down_sync(0xffffffffu, s00, off);
        s01 += __shfl_down_sync(0xffffffffu, s01, off);
        s10 += __shfl_down_sync(0xffffffffu, s10, off);
        s11 += __shfl_down_sync(0xffffffffu, s11, off);
    }
    __shared__ float sh[4][8];
    int lane = threadIdx.x & 31, w = threadIdx.x >> 5;
    if (lane == 0) { sh[0][w] = s00; sh[1][w] = s01; sh[2][w] = s10; sh[3][w] = s11; }
    __syncthreads();
    if (threadIdx.x < 4) {
        float sum = 0;
        int nw = blockDim.x >> 5;
        for (int k = 0; k < nw; k++) sum += sh[threadIdx.x][k];
        atomicAdd(&g_newadj[threadIdx.x], sum);
    }

    // last finishing block writes the final outputs
    __threadfence();
    __shared__ int s_last;
    if (threadIdx.x == 0) s_last = (atomicAdd(&g_done, 1) == (int)gridDim.x - 1);
    __syncthreads();
    if (s_last) {
        int t = threadIdx.x;   // 256 threads
        float g0 = g_group[t], g1 = g_group[256 + t];
        out[t]        = 0.5f * (g0 + g1);
        out[256 + t]  = fminf(fmaxf(g0, -100.0f), 100.0f);
        out[512 + t]  = fminf(fmaxf(g1, -100.0f), 100.0f);
        if (t == 0) {
            float n00 = g_newadj[0], n01 = g_newadj[1];
            float n10 = g_newadj[2], n11 = g_newadj[3];
            float d0 = fmaxf(fabsf(n00) + fabsf(n01), 1e-12f);
            float d1 = fmaxf(fabsf(n10) + fabsf(n11), 1e-12f);
            float diag0 = n00 / d0 - 1.0f;
            float diag1 = n11 / d1 - 1.0f;
            out[768] = 0.5f * (diag0 * diag0 + diag1 * diag1);
        }
    }
}

// ---------------- launch ------------------------------------------------------

extern "C" void kernel_launch(void* const* d_in, const int* in_sizes, int n_in,
                              void* d_out, int out_size) {
    const float* features = (const float*)d_in[0];
    const int*   edges    = (const int*)d_in[1];
    const float* W1   = (const float*)d_in[2];
    const float* b1   = (const float*)d_in[3];
    const float* W2   = (const float*)d_in[4];
    const float* b2   = (const float*)d_in[5];
    const float* fc1w = (const float*)d_in[6];
    const float* fc1b = (const float*)d_in[7];
    const float* fc2w = (const float*)d_in[8];
    const float* fc2b = (const float*)d_in[9];
    float* out = (float*)d_out;

    const int n = in_sizes[0] / F_IN;       // 16384
    const int E = in_sizes[1] / 2;          // 524288
    const int* src = edges;
    const int* dst = edges + E;

    float* bufB;
    __half *aggXh, *bufAh, *xwh, *w1h, *w2h;
    cudaGetSymbolAddress((void**)&aggXh, g_aggXh);
    cudaGetSymbolAddress((void**)&bufAh, g_bufAh);
    cudaGetSymbolAddress((void**)&xwh,   g_xwh);
    cudaGetSymbolAddress((void**)&bufB,  g_bufB);
    cudaGetSymbolAddress((void**)&w1h,   g_w1h);
    cudaGetSymbolAddress((void**)&w2h,   g_w2h);

    // ---- preprocessing
    zero_kernel<<<(n * F_IN / 4 + 255) / 256, 256>>>(fc1w, W1, W2, features);
    deg_kernel<<<(E + 255) / 256, 256>>>(dst, E);
    scan_kernel<<<1, 1024>>>();
    fill_kernel<<<(E / 2 + 255) / 256, 256>>>(src, dst, E);

    // ---- layer 1: relu((agg X) W1 + b1)  (all-fp16 GEMM datapath)
    gather128h_kernel<<<n / 8, 256>>>();
    {
        dim3 grid(H1 / 128, n / 128);
        hgemm_kernel<2, true><<<grid, 256>>>(aggXh, w1h, bufAh, b1, n, F_IN, H1);
    }

    // ---- layer 2: agg(h1 W2) + b2
    {
        dim3 grid(H2 / 128, n / 128);
        hgemm_kernel<0, true><<<grid, 256>>>(bufAh, w2h, xwh, nullptr, n, H1, H2);
    }
    gather256h_kernel<<<n, 64>>>(b2, bufB);

    // ---- assignment MLP + softmax + group features (fused)
    mlp_kernel<<<n / 32, 256>>>(bufB, fc1b, fc2w, fc2b);

    // ---- 2x2 pooled adjacency + final outputs (fused)
    newadj_kernel<<<256, 256>>>(src, dst, E, out);
}